// round 10
// baseline (speedup 1.0000x reference)
#include <cuda_runtime.h>
#include <cuda_fp16.h>
#include <cstdint>

typedef unsigned short u16;
typedef unsigned int   u32;
typedef unsigned long long u64;

#define NTOK 8192
#define DIM  1024
#define HID  2048
#define NE   8
#define MAXROWS 17408
#define MAXMT 136

__device__ int   g_counts[NE], g_fill[NE], g_ntiles;
__device__ int   g_tile_expert[MAXMT], g_tile_row0[MAXMT];
__device__ int   g_row_token[MAXROWS];
__device__ float g_row_coef[MAXROWS];
__device__ int   g_tok_e[NTOK * 2];
__device__ float g_tok_p[NTOK * 2];

__device__ __align__(16) u16 g_Xhi[(size_t)MAXROWS * DIM];
__device__ __align__(16) u16 g_W1hi[(size_t)NE * HID * DIM];
__device__ __align__(16) u16 g_W3hi[(size_t)NE * HID * DIM];
__device__ __align__(16) u16 g_W2hi[(size_t)NE * DIM * HID];
__device__ __align__(16) u16 g_Hhi[(size_t)MAXROWS * HID];

__device__ __forceinline__ u16 f2h(float f) { return __half_as_ushort(__float2half_rn(f)); }
__device__ __forceinline__ u32 pk(u16 a, u16 b) { return (u32)a | ((u32)b << 16); }

__device__ __forceinline__ u32 smem_u32(const void* p) {
    u32 a;
    asm("{ .reg .u64 t; cvta.to.shared.u64 t, %1; cvt.u32.u64 %0, t; }" : "=r"(a) : "l"(p));
    return a;
}
__device__ __forceinline__ void cpa16(u32 dst, const void* src) {
    asm volatile("cp.async.cg.shared.global [%0], [%1], 16;" :: "r"(dst), "l"(src) : "memory");
}
__device__ __forceinline__ void cpa_commit() { asm volatile("cp.async.commit_group;" ::: "memory"); }
__device__ __forceinline__ void cpa_wait2() { asm volatile("cp.async.wait_group 2;" ::: "memory"); }

__device__ __forceinline__ void ldsm4(u32* r, u32 addr) {
    asm volatile("ldmatrix.sync.aligned.m8n8.x4.shared.b16 {%0,%1,%2,%3}, [%4];"
                 : "=r"(r[0]), "=r"(r[1]), "=r"(r[2]), "=r"(r[3]) : "r"(addr));
}
__device__ __forceinline__ void mma16816(float* c, const u32* a, const u32* b) {
    asm volatile(
        "mma.sync.aligned.m16n8k16.row.col.f32.f16.f16.f32 "
        "{%0,%1,%2,%3}, {%4,%5,%6,%7}, {%8,%9}, {%0,%1,%2,%3};"
        : "+f"(c[0]), "+f"(c[1]), "+f"(c[2]), "+f"(c[3])
        : "r"(a[0]), "r"(a[1]), "r"(a[2]), "r"(a[3]), "r"(b[0]), "r"(b[1]));
}

// ---------------- prep: init + weight fp16 conversion + zero Xhi/out ----------------
// blocks [0,16384) W1 ; [16384,32768) W3 ; [32768,49152) W2 ;
// [49152,57856) zero Xhi ; [57856,66048) zero out
__global__ void k_prep(const float* __restrict__ W1, const float* __restrict__ W2,
                       const float* __restrict__ W3, float* __restrict__ out) {
    int b = blockIdx.x;
    if (b < 68) {
        int i = b * 256 + threadIdx.x;
        if (i < MAXROWS) { g_row_token[i] = -1; g_row_coef[i] = 0.f; }
        if (i < NE) { g_counts[i] = 0; g_fill[i] = 0; }
    }
    if (b < 49152) {
        int which = b >> 14;
        size_t i = ((size_t)(b & 16383) * 256 + threadIdx.x) * 4;
        const float* src = (which == 0) ? W1 : (which == 1) ? W3 : W2;
        u16* dst = (which == 0) ? g_W1hi : (which == 1) ? g_W3hi : g_W2hi;
        float4 v = *(const float4*)(src + i);
        *(uint2*)(dst + i) = make_uint2(pk(f2h(v.x), f2h(v.y)), pk(f2h(v.z), f2h(v.w)));
    } else if (b < 57856) {
        size_t i = ((size_t)(b - 49152) * 256 + threadIdx.x) * 8;
        *(uint4*)(g_Xhi + i) = make_uint4(0, 0, 0, 0);
    } else {
        size_t i = ((size_t)(b - 57856) * 256 + threadIdx.x) * 4;
        *(float4*)(out + i) = make_float4(0.f, 0.f, 0.f, 0.f);
    }
}

__global__ void k_gate(const float* __restrict__ x, const float* __restrict__ gw,
                       const float* __restrict__ gb) {
    int w = (blockIdx.x * blockDim.x + threadIdx.x) >> 5;
    int lane = threadIdx.x & 31;
    if (w >= NTOK) return;
    const float* xr = x + (size_t)w * DIM;
    float acc[NE];
#pragma unroll
    for (int e = 0; e < NE; e++) acc[e] = 0.f;
    for (int j = lane; j < DIM; j += 32) {
        float xv = xr[j];
#pragma unroll
        for (int e = 0; e < NE; e++) acc[e] = fmaf(xv, gw[e * DIM + j], acc[e]);
    }
#pragma unroll
    for (int e = 0; e < NE; e++)
#pragma unroll
        for (int o = 16; o; o >>= 1) acc[e] += __shfl_xor_sync(0xffffffffu, acc[e], o);
    if (lane == 0) {
#pragma unroll
        for (int e = 0; e < NE; e++) acc[e] += gb[e];
        int e0 = 0;
#pragma unroll
        for (int e = 1; e < NE; e++) if (acc[e] > acc[e0]) e0 = e;
        int e1 = (e0 == 0) ? 1 : 0;
#pragma unroll
        for (int e = 0; e < NE; e++) if (e != e0 && acc[e] > acc[e1]) e1 = e;
        float p0 = 1.f / (1.f + expf(acc[e1] - acc[e0]));
        g_tok_e[2 * w] = e0; g_tok_e[2 * w + 1] = e1;
        g_tok_p[2 * w] = p0; g_tok_p[2 * w + 1] = 1.f - p0;
        atomicAdd(&g_counts[e0], 1);
        atomicAdd(&g_counts[e1], 1);
    }
}

// ---------------- route: offsets + assign + gather-X (fused) ----------------
// 32 blocks x 256 threads; block b owns tokens [b*256, (b+1)*256).
__global__ void k_route(const float* __restrict__ x) {
    __shared__ int srow[512];
    int b = blockIdx.x, tid = threadIdx.x;

    // every block redundantly computes the segment prefix from g_counts
    int segs[NE];
    {
        int off = 0;
#pragma unroll
        for (int e = 0; e < NE; e++) {
            segs[e] = off;
            off += ((g_counts[e] + 127) >> 7) << 7;
        }
    }
    if (b == 0 && tid == 0) {
        int nt = 0;
        for (int e = 0; e < NE; e++) {
            int t = (g_counts[e] + 127) >> 7;
            for (int m = 0; m < t; m++) {
                g_tile_expert[nt] = e;
                g_tile_row0[nt] = segs[e] + (m << 7);
                nt++;
            }
        }
        g_ntiles = nt;
    }

    int t = b * 256 + tid;
#pragma unroll
    for (int k = 0; k < 2; k++) {
        int e = g_tok_e[2 * t + k];
        int row = segs[e] + atomicAdd(&g_fill[e], 1);
        g_row_token[row] = t;
        g_row_coef[row] = g_tok_p[2 * t + k];
        srow[tid * 2 + k] = row;
    }
    __syncthreads();

    // copy phase: 8 warps cover 512 (token,slot) rows
    int wid = tid >> 5, lane = tid & 31;
    for (int rr = wid; rr < 512; rr += 8) {
        int row = srow[rr];
        int tok = b * 256 + (rr >> 1);
        const float4* src = (const float4*)(x + (size_t)tok * DIM);
        u16* dst = g_Xhi + (size_t)row * DIM;
#pragma unroll
        for (int j = lane; j < 256; j += 32) {
            float4 v = src[j];
            *(uint2*)(dst + j * 4) = make_uint2(pk(f2h(v.x), f2h(v.y)), pk(f2h(v.z), f2h(v.w)));
        }
    }
}

// ---------------- GEMM13: H = relu(X W1^T)^2 * (X W3^T) ----------------
// CTA 128x128, 512 threads (16 warps), warp tile 32x32, BK=32, 4-stage.
#define RS 80
#define S13_A  0
#define S13_B1 10240
#define S13_B3 20480
#define SS13 30720
#define SMEM13 (4 * SS13)

__device__ __forceinline__ void load13(u32 sbase, int stage, int kt,
                                       const u16* Ah, size_t wbase, int tid) {
    int k0 = kt * 32;
    u32 st = sbase + stage * SS13;
#pragma unroll
    for (int it = 0; it < 3; it++) {
        int c = tid + it * 512;
        int r = (c >> 2) & 127, ch = c & 3;
        u32 dst; const u16* src;
        if (c < 512)       { dst = st + S13_A + r * RS + ch * 16; src = Ah + (size_t)r * DIM + k0 + ch * 8; }
        else if (c < 1024) { dst = st + S13_B1 + r * RS + ch * 16; src = g_W1hi + (wbase + r) * DIM + k0 + ch * 8; }
        else               { dst = st + S13_B3 + r * RS + ch * 16; src = g_W3hi + (wbase + r) * DIM + k0 + ch * 8; }
        cpa16(dst, src);
    }
}

__global__ __launch_bounds__(512, 1)
void k_gemm13() {
    if ((int)blockIdx.x >= g_ntiles) return;
    extern __shared__ char smraw[];
    u32 sbase = smem_u32(smraw);
    int tid = threadIdx.x, wid = tid >> 5, lane = tid & 31;
    int warpM = wid >> 2, warpN = wid & 3;
    int e = g_tile_expert[blockIdx.x], row0 = g_tile_row0[blockIdx.x];
    int n0w = blockIdx.y * 128;

    const u16* Ah = g_Xhi + (size_t)row0 * DIM;
    size_t wbase = (size_t)e * HID + n0w;

    u32 aoff = (u32)((lane & 15) * RS + (lane >> 4) * 16);
    u32 b4off = (u32)(((lane & 7) + ((lane >> 4) << 3)) * RS + ((lane >> 3) & 1) * 16);
    u32 aW = (u32)(warpM * 32 * RS);
    u32 bW = (u32)(warpN * 32 * RS);

    float acc1[2][4][4], acc3[2][4][4];
#pragma unroll
    for (int mt = 0; mt < 2; mt++)
#pragma unroll
        for (int nt = 0; nt < 4; nt++)
#pragma unroll
            for (int j = 0; j < 4; j++) { acc1[mt][nt][j] = 0.f; acc3[mt][nt][j] = 0.f; }

    const int KT = DIM / 32;
    load13(sbase, 0, 0, Ah, wbase, tid); cpa_commit();
    load13(sbase, 1, 1, Ah, wbase, tid); cpa_commit();
    load13(sbase, 2, 2, Ah, wbase, tid); cpa_commit();

    for (int kt = 0; kt < KT; kt++) {
        cpa_wait2();
        __syncthreads();
        if (kt + 3 < KT) load13(sbase, (kt + 3) & 3, kt + 3, Ah, wbase, tid);
        cpa_commit();
        u32 st = sbase + (kt & 3) * SS13;
#pragma unroll
        for (int kh = 0; kh < 2; kh++) {
            u32 AH[2][4];
#pragma unroll
            for (int mt = 0; mt < 2; mt++)
                ldsm4(AH[mt], st + S13_A + aW + mt * 16 * RS + kh * 32 + aoff);
#pragma unroll
            for (int ntp = 0; ntp < 2; ntp++) {
                u32 nb = bW + ntp * 16 * RS + kh * 32 + b4off;
                u32 b1[4], b3[4];
                ldsm4(b1, st + S13_B1 + nb);
                ldsm4(b3, st + S13_B3 + nb);
#pragma unroll
                for (int sub = 0; sub < 2; sub++)
#pragma unroll
                    for (int mt = 0; mt < 2; mt++) {
                        mma16816(acc1[mt][ntp * 2 + sub], AH[mt], b1 + sub * 2);
                        mma16816(acc3[mt][ntp * 2 + sub], AH[mt], b3 + sub * 2);
                    }
            }
        }
    }

    int g4 = lane >> 2, t4 = lane & 3;
#pragma unroll
    for (int mt = 0; mt < 2; mt++) {
        int rA = row0 + warpM * 32 + mt * 16 + g4;
#pragma unroll
        for (int nt = 0; nt < 4; nt++) {
            int col = n0w + warpN * 32 + nt * 8 + t4 * 2;
            const float* d1 = acc1[mt][nt];
            const float* d3 = acc3[mt][nt];
#pragma unroll
            for (int half = 0; half < 2; half++) {
                int row = rA + half * 8;
                float r0 = fmaxf(d1[half * 2], 0.f), r1 = fmaxf(d1[half * 2 + 1], 0.f);
                float h0 = r0 * r0 * d3[half * 2];
                float h1 = r1 * r1 * d3[half * 2 + 1];
                *(u32*)(g_Hhi + (size_t)row * HID + col) = pk(f2h(h0), f2h(h1));
            }
        }
    }
}

// ---------------- GEMM2: out += coef * (H W2^T) via atomic scatter ----------------
// CTA 128x128, 512 threads, warp tile 32x32, BK=32, 4-stage.
#define S2_A 0
#define S2_B 10240
#define SS2 20480
#define SMEM2 (4 * SS2)

__device__ __forceinline__ void load2(u32 sbase, int stage, int kt,
                                      const u16* Ah, size_t wbase, int tid) {
    int k0 = kt * 32;
    u32 st = sbase + stage * SS2;
#pragma unroll
    for (int it = 0; it < 2; it++) {
        int c = tid + it * 512;
        int r = (c >> 2) & 127, ch = c & 3;
        u32 dst; const u16* src;
        if (c < 512) { dst = st + S2_A + r * RS + ch * 16; src = Ah + (size_t)r * HID + k0 + ch * 8; }
        else         { dst = st + S2_B + r * RS + ch * 16; src = g_W2hi + (wbase + r) * HID + k0 + ch * 8; }
        cpa16(dst, src);
    }
}

__global__ __launch_bounds__(512, 1)
void k_gemm2(float* __restrict__ out) {
    if ((int)blockIdx.x >= g_ntiles) return;
    extern __shared__ char smraw[];
    u32 sbase = smem_u32(smraw);
    int tid = threadIdx.x, wid = tid >> 5, lane = tid & 31;
    int warpM = wid >> 2, warpN = wid & 3;
    int e = g_tile_expert[blockIdx.x], row0 = g_tile_row0[blockIdx.x];
    int n0w = blockIdx.y * 128;

    const u16* Ah = g_Hhi + (size_t)row0 * HID;
    size_t wbase = (size_t)e * DIM + n0w;

    u32 aoff = (u32)((lane & 15) * RS + (lane >> 4) * 16);
    u32 b4off = (u32)(((lane & 7) + ((lane >> 4) << 3)) * RS + ((lane >> 3) & 1) * 16);
    u32 aW = (u32)(warpM * 32 * RS);
    u32 bW = (u32)(warpN * 32 * RS);

    float acc[2][4][4];
#pragma unroll
    for (int mt = 0; mt < 2; mt++)
#pragma unroll
        for (int nt = 0; nt < 4; nt++)
#pragma unroll
            for (int j = 0; j < 4; j++) acc[mt][nt][j] = 0.f;

    const int KT = HID / 32;
    load2(sbase, 0, 0, Ah, wbase, tid); cpa_commit();
    load2(sbase, 1, 1, Ah, wbase, tid); cpa_commit();
    load2(sbase, 2, 2, Ah, wbase, tid); cpa_commit();

    for (int kt = 0; kt < KT; kt++) {
        cpa_wait2();
        __syncthreads();
        if (kt + 3 < KT) load2(sbase, (kt + 3) & 3, kt + 3, Ah, wbase, tid);
        cpa_commit();
        u32 st = sbase + (kt & 3) * SS2;
#pragma unroll
        for (int kh = 0; kh < 2; kh++) {
            u32 AH[2][4];
#pragma unroll
            for (int mt = 0; mt < 2; mt++)
                ldsm4(AH[mt], st + S2_A + aW + mt * 16 * RS + kh * 32 + aoff);
#pragma unroll
            for (int ntp = 0; ntp < 2; ntp++) {
                u32 bh[4];
                ldsm4(bh, st + S2_B + bW + ntp * 16 * RS + kh * 32 + b4off);
#pragma unroll
                for (int sub = 0; sub < 2; sub++)
#pragma unroll
                    for (int mt = 0; mt < 2; mt++)
                        mma16816(acc[mt][ntp * 2 + sub], AH[mt], bh + sub * 2);
            }
        }
    }

    int g4 = lane >> 2, t4 = lane & 3;
#pragma unroll
    for (int mt = 0; mt < 2; mt++) {
        int rA = row0 + warpM * 32 + mt * 16 + g4;
        int t0 = g_row_token[rA], t1 = g_row_token[rA + 8];
        float c0 = g_row_coef[rA], c1 = g_row_coef[rA + 8];
#pragma unroll
        for (int nt = 0; nt < 4; nt++) {
            int col = n0w + warpN * 32 + nt * 8 + t4 * 2;
            const float* d = acc[mt][nt];
            if (t0 >= 0) {
                atomicAdd(&out[(size_t)t0 * DIM + col],     c0 * d[0]);
                atomicAdd(&out[(size_t)t0 * DIM + col + 1], c0 * d[1]);
            }
            if (t1 >= 0) {
                atomicAdd(&out[(size_t)t1 * DIM + col],     c1 * d[2]);
                atomicAdd(&out[(size_t)t1 * DIM + col + 1], c1 * d[3]);
            }
        }
    }
}

extern "C" void kernel_launch(void* const* d_in, const int* in_sizes, int n_in,
                              void* d_out, int out_size) {
    const float* x  = (const float*)d_in[0];
    const float* W1 = (const float*)d_in[1];
    const float* W2 = (const float*)d_in[2];
    const float* W3 = (const float*)d_in[3];
    const float* gw = (const float*)d_in[4];
    const float* gb = (const float*)d_in[5];
    float* out = (float*)d_out;

    cudaFuncSetAttribute(k_gemm13, cudaFuncAttributeMaxDynamicSharedMemorySize, SMEM13);
    cudaFuncSetAttribute(k_gemm2,  cudaFuncAttributeMaxDynamicSharedMemorySize, SMEM2);

    k_prep<<<66048, 256>>>(W1, W2, W3, out);
    k_gate<<<1024, 256>>>(x, gw, gb);
    k_route<<<32, 256>>>(x);
    k_gemm13<<<dim3(MAXMT, HID / 128), 512, SMEM13>>>();
    k_gemm2<<<dim3(MAXMT, DIM / 128), 512, SMEM2>>>(out);
}

// round 11
// speedup vs baseline: 1.0019x; 1.0019x over previous
#include <cuda_runtime.h>
#include <cuda_fp16.h>
#include <cstdint>

typedef unsigned short u16;
typedef unsigned int   u32;
typedef unsigned long long u64;

#define NTOK 8192
#define DIM  1024
#define HID  2048
#define NE   8
#define MAXROWS 17408
#define MAXMT 136

__device__ int   g_counts[NE], g_fill[NE], g_ntiles;
__device__ int   g_tile_expert[MAXMT], g_tile_row0[MAXMT];
__device__ int   g_row_token[MAXROWS];
__device__ float g_row_coef[MAXROWS];
__device__ int   g_token_row[NTOK * 2];
__device__ int   g_tok_e[NTOK * 2];
__device__ float g_tok_p[NTOK * 2];

__device__ __align__(16) u16 g_Xhi[(size_t)MAXROWS * DIM];
__device__ __align__(16) u16 g_W1hi[(size_t)NE * HID * DIM];
__device__ __align__(16) u16 g_W3hi[(size_t)NE * HID * DIM];
__device__ __align__(16) u16 g_W2hi[(size_t)NE * DIM * HID];
__device__ __align__(16) u16 g_Hhi[(size_t)MAXROWS * HID];
__device__ __align__(16) float g_Orows[(size_t)MAXROWS * DIM];

__device__ __forceinline__ u16 f2h(float f) { return __half_as_ushort(__float2half_rn(f)); }
__device__ __forceinline__ u32 pk(u16 a, u16 b) { return (u32)a | ((u32)b << 16); }

__device__ __forceinline__ u32 smem_u32(const void* p) {
    u32 a;
    asm("{ .reg .u64 t; cvta.to.shared.u64 t, %1; cvt.u32.u64 %0, t; }" : "=r"(a) : "l"(p));
    return a;
}
__device__ __forceinline__ void cpa16(u32 dst, const void* src) {
    asm volatile("cp.async.cg.shared.global [%0], [%1], 16;" :: "r"(dst), "l"(src) : "memory");
}
__device__ __forceinline__ void cpa_commit() { asm volatile("cp.async.commit_group;" ::: "memory"); }
__device__ __forceinline__ void cpa_wait2() { asm volatile("cp.async.wait_group 2;" ::: "memory"); }

__device__ __forceinline__ void ldsm4(u32* r, u32 addr) {
    asm volatile("ldmatrix.sync.aligned.m8n8.x4.shared.b16 {%0,%1,%2,%3}, [%4];"
                 : "=r"(r[0]), "=r"(r[1]), "=r"(r[2]), "=r"(r[3]) : "r"(addr));
}
__device__ __forceinline__ void mma16816(float* c, const u32* a, const u32* b) {
    asm volatile(
        "mma.sync.aligned.m16n8k16.row.col.f32.f16.f16.f32 "
        "{%0,%1,%2,%3}, {%4,%5,%6,%7}, {%8,%9}, {%0,%1,%2,%3};"
        : "+f"(c[0]), "+f"(c[1]), "+f"(c[2]), "+f"(c[3])
        : "r"(a[0]), "r"(a[1]), "r"(a[2]), "r"(a[3]), "r"(b[0]), "r"(b[1]));
}

// ---------------- prep: init + weight fp16 conversion + zero Xhi ----------------
// blocks [0,16384) W1 ; [16384,32768) W3 ; [32768,49152) W2 ; [49152,57856) zero Xhi
__global__ void k_prep(const float* __restrict__ W1, const float* __restrict__ W2,
                       const float* __restrict__ W3) {
    int b = blockIdx.x;
    if (b < 68) {
        int i = b * 256 + threadIdx.x;
        if (i < MAXROWS) { g_row_token[i] = -1; g_row_coef[i] = 0.f; }
        if (i < NE) { g_counts[i] = 0; g_fill[i] = 0; }
    }
    if (b < 49152) {
        int which = b >> 14;
        size_t i = ((size_t)(b & 16383) * 256 + threadIdx.x) * 4;
        const float* src = (which == 0) ? W1 : (which == 1) ? W3 : W2;
        u16* dst = (which == 0) ? g_W1hi : (which == 1) ? g_W3hi : g_W2hi;
        float4 v = *(const float4*)(src + i);
        *(uint2*)(dst + i) = make_uint2(pk(f2h(v.x), f2h(v.y)), pk(f2h(v.z), f2h(v.w)));
    } else {
        size_t i = ((size_t)(b - 49152) * 256 + threadIdx.x) * 8;
        *(uint4*)(g_Xhi + i) = make_uint4(0, 0, 0, 0);
    }
}

__global__ void k_gate(const float* __restrict__ x, const float* __restrict__ gw,
                       const float* __restrict__ gb) {
    int w = (blockIdx.x * blockDim.x + threadIdx.x) >> 5;
    int lane = threadIdx.x & 31;
    if (w >= NTOK) return;
    const float* xr = x + (size_t)w * DIM;
    float acc[NE];
#pragma unroll
    for (int e = 0; e < NE; e++) acc[e] = 0.f;
    for (int j = lane; j < DIM; j += 32) {
        float xv = xr[j];
#pragma unroll
        for (int e = 0; e < NE; e++) acc[e] = fmaf(xv, gw[e * DIM + j], acc[e]);
    }
#pragma unroll
    for (int e = 0; e < NE; e++)
#pragma unroll
        for (int o = 16; o; o >>= 1) acc[e] += __shfl_xor_sync(0xffffffffu, acc[e], o);
    if (lane == 0) {
#pragma unroll
        for (int e = 0; e < NE; e++) acc[e] += gb[e];
        int e0 = 0;
#pragma unroll
        for (int e = 1; e < NE; e++) if (acc[e] > acc[e0]) e0 = e;
        int e1 = (e0 == 0) ? 1 : 0;
#pragma unroll
        for (int e = 0; e < NE; e++) if (e != e0 && acc[e] > acc[e1]) e1 = e;
        float p0 = 1.f / (1.f + expf(acc[e1] - acc[e0]));
        g_tok_e[2 * w] = e0; g_tok_e[2 * w + 1] = e1;
        g_tok_p[2 * w] = p0; g_tok_p[2 * w + 1] = 1.f - p0;
        atomicAdd(&g_counts[e0], 1);
        atomicAdd(&g_counts[e1], 1);
    }
}

// ---------------- route: offsets + assign + gather-X (fused) ----------------
__global__ void k_route(const float* __restrict__ x) {
    __shared__ int srow[512];
    int b = blockIdx.x, tid = threadIdx.x;

    int segs[NE];
    {
        int off = 0;
#pragma unroll
        for (int e = 0; e < NE; e++) {
            segs[e] = off;
            off += ((g_counts[e] + 127) >> 7) << 7;
        }
    }
    if (b == 0 && tid == 0) {
        int nt = 0;
        for (int e = 0; e < NE; e++) {
            int t = (g_counts[e] + 127) >> 7;
            for (int m = 0; m < t; m++) {
                g_tile_expert[nt] = e;
                g_tile_row0[nt] = segs[e] + (m << 7);
                nt++;
            }
        }
        g_ntiles = nt;
    }

    int t = b * 256 + tid;
#pragma unroll
    for (int k = 0; k < 2; k++) {
        int e = g_tok_e[2 * t + k];
        int row = segs[e] + atomicAdd(&g_fill[e], 1);
        g_row_token[row] = t;
        g_row_coef[row] = g_tok_p[2 * t + k];
        g_token_row[2 * t + k] = row;
        srow[tid * 2 + k] = row;
    }
    __syncthreads();

    int wid = tid >> 5, lane = tid & 31;
    for (int rr = wid; rr < 512; rr += 8) {
        int row = srow[rr];
        int tok = b * 256 + (rr >> 1);
        const float4* src = (const float4*)(x + (size_t)tok * DIM);
        u16* dst = g_Xhi + (size_t)row * DIM;
#pragma unroll
        for (int j = lane; j < 256; j += 32) {
            float4 v = src[j];
            *(uint2*)(dst + j * 4) = make_uint2(pk(f2h(v.x), f2h(v.y)), pk(f2h(v.z), f2h(v.w)));
        }
    }
}

// ---------------- GEMM13: H = relu(X W1^T)^2 * (X W3^T) ----------------
// CTA 128x128, 512 threads (16 warps), warp tile 32x32, BK=32, 4-stage.
#define RS 80
#define S13_A  0
#define S13_B1 10240
#define S13_B3 20480
#define SS13 30720
#define SMEM13 (4 * SS13)

__device__ __forceinline__ void load13(u32 sbase, int stage, int kt,
                                       const u16* Ah, size_t wbase, int tid) {
    int k0 = kt * 32;
    u32 st = sbase + stage * SS13;
#pragma unroll
    for (int it = 0; it < 3; it++) {
        int c = tid + it * 512;
        int r = (c >> 2) & 127, ch = c & 3;
        u32 dst; const u16* src;
        if (c < 512)       { dst = st + S13_A + r * RS + ch * 16; src = Ah + (size_t)r * DIM + k0 + ch * 8; }
        else if (c < 1024) { dst = st + S13_B1 + r * RS + ch * 16; src = g_W1hi + (wbase + r) * DIM + k0 + ch * 8; }
        else               { dst = st + S13_B3 + r * RS + ch * 16; src = g_W3hi + (wbase + r) * DIM + k0 + ch * 8; }
        cpa16(dst, src);
    }
}

__global__ __launch_bounds__(512, 1)
void k_gemm13() {
    if ((int)blockIdx.x >= g_ntiles) return;
    extern __shared__ char smraw[];
    u32 sbase = smem_u32(smraw);
    int tid = threadIdx.x, wid = tid >> 5, lane = tid & 31;
    int warpM = wid >> 2, warpN = wid & 3;
    int e = g_tile_expert[blockIdx.x], row0 = g_tile_row0[blockIdx.x];
    int n0w = blockIdx.y * 128;

    const u16* Ah = g_Xhi + (size_t)row0 * DIM;
    size_t wbase = (size_t)e * HID + n0w;

    u32 aoff = (u32)((lane & 15) * RS + (lane >> 4) * 16);
    u32 b4off = (u32)(((lane & 7) + ((lane >> 4) << 3)) * RS + ((lane >> 3) & 1) * 16);
    u32 aW = (u32)(warpM * 32 * RS);
    u32 bW = (u32)(warpN * 32 * RS);

    float acc1[2][4][4], acc3[2][4][4];
#pragma unroll
    for (int mt = 0; mt < 2; mt++)
#pragma unroll
        for (int nt = 0; nt < 4; nt++)
#pragma unroll
            for (int j = 0; j < 4; j++) { acc1[mt][nt][j] = 0.f; acc3[mt][nt][j] = 0.f; }

    const int KT = DIM / 32;
    load13(sbase, 0, 0, Ah, wbase, tid); cpa_commit();
    load13(sbase, 1, 1, Ah, wbase, tid); cpa_commit();
    load13(sbase, 2, 2, Ah, wbase, tid); cpa_commit();

    for (int kt = 0; kt < KT; kt++) {
        cpa_wait2();
        __syncthreads();
        if (kt + 3 < KT) load13(sbase, (kt + 3) & 3, kt + 3, Ah, wbase, tid);
        cpa_commit();
        u32 st = sbase + (kt & 3) * SS13;
#pragma unroll
        for (int kh = 0; kh < 2; kh++) {
            u32 AH[2][4];
#pragma unroll
            for (int mt = 0; mt < 2; mt++)
                ldsm4(AH[mt], st + S13_A + aW + mt * 16 * RS + kh * 32 + aoff);
#pragma unroll
            for (int ntp = 0; ntp < 2; ntp++) {
                u32 nb = bW + ntp * 16 * RS + kh * 32 + b4off;
                u32 b1[4], b3[4];
                ldsm4(b1, st + S13_B1 + nb);
                ldsm4(b3, st + S13_B3 + nb);
#pragma unroll
                for (int sub = 0; sub < 2; sub++)
#pragma unroll
                    for (int mt = 0; mt < 2; mt++) {
                        mma16816(acc1[mt][ntp * 2 + sub], AH[mt], b1 + sub * 2);
                        mma16816(acc3[mt][ntp * 2 + sub], AH[mt], b3 + sub * 2);
                    }
            }
        }
    }

    int g4 = lane >> 2, t4 = lane & 3;
#pragma unroll
    for (int mt = 0; mt < 2; mt++) {
        int rA = row0 + warpM * 32 + mt * 16 + g4;
#pragma unroll
        for (int nt = 0; nt < 4; nt++) {
            int col = n0w + warpN * 32 + nt * 8 + t4 * 2;
            const float* d1 = acc1[mt][nt];
            const float* d3 = acc3[mt][nt];
#pragma unroll
            for (int half = 0; half < 2; half++) {
                int row = rA + half * 8;
                float r0 = fmaxf(d1[half * 2], 0.f), r1 = fmaxf(d1[half * 2 + 1], 0.f);
                float h0 = r0 * r0 * d3[half * 2];
                float h1 = r1 * r1 * d3[half * 2 + 1];
                *(u32*)(g_Hhi + (size_t)row * HID + col) = pk(f2h(h0), f2h(h1));
            }
        }
    }
}

// ---------------- GEMM2: Orows = coef * (H W2^T) ----------------
// CTA 128x128, 512 threads, warp tile 32x32, BK=32, 4-stage.
#define S2_A 0
#define S2_B 10240
#define SS2 20480
#define SMEM2 (4 * SS2)

__device__ __forceinline__ void load2(u32 sbase, int stage, int kt,
                                      const u16* Ah, size_t wbase, int tid) {
    int k0 = kt * 32;
    u32 st = sbase + stage * SS2;
#pragma unroll
    for (int it = 0; it < 2; it++) {
        int c = tid + it * 512;
        int r = (c >> 2) & 127, ch = c & 3;
        u32 dst; const u16* src;
        if (c < 512) { dst = st + S2_A + r * RS + ch * 16; src = Ah + (size_t)r * HID + k0 + ch * 8; }
        else         { dst = st + S2_B + r * RS + ch * 16; src = g_W2hi + (wbase + r) * HID + k0 + ch * 8; }
        cpa16(dst, src);
    }
}

__global__ __launch_bounds__(512, 1)
void k_gemm2() {
    if ((int)blockIdx.x >= g_ntiles) return;
    extern __shared__ char smraw[];
    u32 sbase = smem_u32(smraw);
    int tid = threadIdx.x, wid = tid >> 5, lane = tid & 31;
    int warpM = wid >> 2, warpN = wid & 3;
    int e = g_tile_expert[blockIdx.x], row0 = g_tile_row0[blockIdx.x];
    int n0w = blockIdx.y * 128;

    const u16* Ah = g_Hhi + (size_t)row0 * HID;
    size_t wbase = (size_t)e * DIM + n0w;

    u32 aoff = (u32)((lane & 15) * RS + (lane >> 4) * 16);
    u32 b4off = (u32)(((lane & 7) + ((lane >> 4) << 3)) * RS + ((lane >> 3) & 1) * 16);
    u32 aW = (u32)(warpM * 32 * RS);
    u32 bW = (u32)(warpN * 32 * RS);

    float acc[2][4][4];
#pragma unroll
    for (int mt = 0; mt < 2; mt++)
#pragma unroll
        for (int nt = 0; nt < 4; nt++)
#pragma unroll
            for (int j = 0; j < 4; j++) acc[mt][nt][j] = 0.f;

    const int KT = HID / 32;
    load2(sbase, 0, 0, Ah, wbase, tid); cpa_commit();
    load2(sbase, 1, 1, Ah, wbase, tid); cpa_commit();
    load2(sbase, 2, 2, Ah, wbase, tid); cpa_commit();

    for (int kt = 0; kt < KT; kt++) {
        cpa_wait2();
        __syncthreads();
        if (kt + 3 < KT) load2(sbase, (kt + 3) & 3, kt + 3, Ah, wbase, tid);
        cpa_commit();
        u32 st = sbase + (kt & 3) * SS2;
#pragma unroll
        for (int kh = 0; kh < 2; kh++) {
            u32 AH[2][4];
#pragma unroll
            for (int mt = 0; mt < 2; mt++)
                ldsm4(AH[mt], st + S2_A + aW + mt * 16 * RS + kh * 32 + aoff);
#pragma unroll
            for (int ntp = 0; ntp < 2; ntp++) {
                u32 bh[4];
                ldsm4(bh, st + S2_B + bW + ntp * 16 * RS + kh * 32 + b4off);
#pragma unroll
                for (int sub = 0; sub < 2; sub++)
#pragma unroll
                    for (int mt = 0; mt < 2; mt++)
                        mma16816(acc[mt][ntp * 2 + sub], AH[mt], bh + sub * 2);
            }
        }
    }

    int g4 = lane >> 2, t4 = lane & 3;
#pragma unroll
    for (int mt = 0; mt < 2; mt++) {
        int rA = row0 + warpM * 32 + mt * 16 + g4;
        float c0 = g_row_coef[rA], c1 = g_row_coef[rA + 8];
#pragma unroll
        for (int nt = 0; nt < 4; nt++) {
            int col = n0w + warpN * 32 + nt * 8 + t4 * 2;
            const float* d = acc[mt][nt];
            *(float2*)(g_Orows + (size_t)rA * DIM + col) = make_float2(c0 * d[0], c0 * d[1]);
            *(float2*)(g_Orows + (size_t)(rA + 8) * DIM + col) = make_float2(c1 * d[2], c1 * d[3]);
        }
    }
}

__global__ void k_combine(float* __restrict__ out) {
    int t = blockIdx.x;
    int i = threadIdx.x * 4;
    int r0 = g_token_row[2 * t], r1 = g_token_row[2 * t + 1];
    float4 a = *(const float4*)(g_Orows + (size_t)r0 * DIM + i);
    float4 b = *(const float4*)(g_Orows + (size_t)r1 * DIM + i);
    *(float4*)(out + (size_t)t * DIM + i) =
        make_float4(a.x + b.x, a.y + b.y, a.z + b.z, a.w + b.w);
}

extern "C" void kernel_launch(void* const* d_in, const int* in_sizes, int n_in,
                              void* d_out, int out_size) {
    const float* x  = (const float*)d_in[0];
    const float* W1 = (const float*)d_in[1];
    const float* W2 = (const float*)d_in[2];
    const float* W3 = (const float*)d_in[3];
    const float* gw = (const float*)d_in[4];
    const float* gb = (const float*)d_in[5];
    float* out = (float*)d_out;

    cudaFuncSetAttribute(k_gemm13, cudaFuncAttributeMaxDynamicSharedMemorySize, SMEM13);
    cudaFuncSetAttribute(k_gemm2,  cudaFuncAttributeMaxDynamicSharedMemorySize, SMEM2);

    k_prep<<<57856, 256>>>(W1, W2, W3);
    k_gate<<<1024, 256>>>(x, gw, gb);
    k_route<<<32, 256>>>(x);
    k_gemm13<<<dim3(MAXMT, HID / 128), 512, SMEM13>>>();
    k_gemm2<<<dim3(MAXMT, DIM / 128), 512, SMEM2>>>();
    k_combine<<<NTOK, 256>>>(out);
}

// round 12
// speedup vs baseline: 1.0485x; 1.0465x over previous
#include <cuda_runtime.h>
#include <cuda_fp16.h>
#include <cstdint>

typedef unsigned short u16;
typedef unsigned int   u32;
typedef unsigned long long u64;

#define NTOK 8192
#define DIM  1024
#define HID  2048
#define NE   8
#define MAXROWS 17408
#define MAXMT 136

__device__ int   g_counts[NE], g_fill[NE], g_ntiles;
__device__ int   g_tile_expert[MAXMT], g_tile_row0[MAXMT];
__device__ int   g_row_token[MAXROWS];
__device__ float g_row_coef[MAXROWS];
__device__ int   g_token_row[NTOK * 2];
__device__ int   g_tok_e[NTOK * 2];
__device__ float g_tok_p[NTOK * 2];

__device__ __align__(16) u16 g_Xhi[(size_t)MAXROWS * DIM];
__device__ __align__(16) u16 g_W1hi[(size_t)NE * HID * DIM];
__device__ __align__(16) u16 g_W3hi[(size_t)NE * HID * DIM];
__device__ __align__(16) u16 g_W2hi[(size_t)NE * DIM * HID];
__device__ __align__(16) u16 g_Hhi[(size_t)MAXROWS * HID];
__device__ __align__(16) float g_Orows[(size_t)MAXROWS * DIM];

__device__ __forceinline__ u16 f2h(float f) { return __half_as_ushort(__float2half_rn(f)); }
__device__ __forceinline__ u32 pk(u16 a, u16 b) { return (u32)a | ((u32)b << 16); }

__device__ __forceinline__ u32 smem_u32(const void* p) {
    u32 a;
    asm("{ .reg .u64 t; cvta.to.shared.u64 t, %1; cvt.u32.u64 %0, t; }" : "=r"(a) : "l"(p));
    return a;
}
__device__ __forceinline__ void cpa16(u32 dst, const void* src) {
    asm volatile("cp.async.cg.shared.global [%0], [%1], 16;" :: "r"(dst), "l"(src) : "memory");
}
__device__ __forceinline__ void cpa_commit() { asm volatile("cp.async.commit_group;" ::: "memory"); }
__device__ __forceinline__ void cpa_wait2() { asm volatile("cp.async.wait_group 2;" ::: "memory"); }

__device__ __forceinline__ void ldsm4(u32* r, u32 addr) {
    asm volatile("ldmatrix.sync.aligned.m8n8.x4.shared.b16 {%0,%1,%2,%3}, [%4];"
                 : "=r"(r[0]), "=r"(r[1]), "=r"(r[2]), "=r"(r[3]) : "r"(addr));
}
__device__ __forceinline__ void mma16816(float* c, const u32* a, const u32* b) {
    asm volatile(
        "mma.sync.aligned.m16n8k16.row.col.f32.f16.f16.f32 "
        "{%0,%1,%2,%3}, {%4,%5,%6,%7}, {%8,%9}, {%0,%1,%2,%3};"
        : "+f"(c[0]), "+f"(c[1]), "+f"(c[2]), "+f"(c[3])
        : "r"(a[0]), "r"(a[1]), "r"(a[2]), "r"(a[3]), "r"(b[0]), "r"(b[1]));
}

// ---------------- prep: init + weight fp16 conversion + zero Xhi ----------------
__global__ void k_prep(const float* __restrict__ W1, const float* __restrict__ W2,
                       const float* __restrict__ W3) {
    int b = blockIdx.x;
    if (b < 68) {
        int i = b * 256 + threadIdx.x;
        if (i < MAXROWS) { g_row_token[i] = -1; g_row_coef[i] = 0.f; }
        if (i < NE) { g_counts[i] = 0; g_fill[i] = 0; }
    }
    if (b < 49152) {
        int which = b >> 14;
        size_t i = ((size_t)(b & 16383) * 256 + threadIdx.x) * 4;
        const float* src = (which == 0) ? W1 : (which == 1) ? W3 : W2;
        u16* dst = (which == 0) ? g_W1hi : (which == 1) ? g_W3hi : g_W2hi;
        float4 v = *(const float4*)(src + i);
        *(uint2*)(dst + i) = make_uint2(pk(f2h(v.x), f2h(v.y)), pk(f2h(v.z), f2h(v.w)));
    } else {
        size_t i = ((size_t)(b - 49152) * 256 + threadIdx.x) * 8;
        *(uint4*)(g_Xhi + i) = make_uint4(0, 0, 0, 0);
    }
}

__global__ void k_gate(const float* __restrict__ x, const float* __restrict__ gw,
                       const float* __restrict__ gb) {
    int w = (blockIdx.x * blockDim.x + threadIdx.x) >> 5;
    int lane = threadIdx.x & 31;
    if (w >= NTOK) return;
    const float* xr = x + (size_t)w * DIM;
    float acc[NE];
#pragma unroll
    for (int e = 0; e < NE; e++) acc[e] = 0.f;
    for (int j = lane; j < DIM; j += 32) {
        float xv = xr[j];
#pragma unroll
        for (int e = 0; e < NE; e++) acc[e] = fmaf(xv, gw[e * DIM + j], acc[e]);
    }
#pragma unroll
    for (int e = 0; e < NE; e++)
#pragma unroll
        for (int o = 16; o; o >>= 1) acc[e] += __shfl_xor_sync(0xffffffffu, acc[e], o);
    if (lane == 0) {
#pragma unroll
        for (int e = 0; e < NE; e++) acc[e] += gb[e];
        int e0 = 0;
#pragma unroll
        for (int e = 1; e < NE; e++) if (acc[e] > acc[e0]) e0 = e;
        int e1 = (e0 == 0) ? 1 : 0;
#pragma unroll
        for (int e = 0; e < NE; e++) if (e != e0 && acc[e] > acc[e1]) e1 = e;
        float p0 = 1.f / (1.f + expf(acc[e1] - acc[e0]));
        g_tok_e[2 * w] = e0; g_tok_e[2 * w + 1] = e1;
        g_tok_p[2 * w] = p0; g_tok_p[2 * w + 1] = 1.f - p0;
        atomicAdd(&g_counts[e0], 1);
        atomicAdd(&g_counts[e1], 1);
    }
}

// ---------------- route: offsets + assign (fused, 32 blocks) ----------------
__global__ void k_route() {
    int b = blockIdx.x, tid = threadIdx.x;

    int segs[NE];
    {
        int off = 0;
#pragma unroll
        for (int e = 0; e < NE; e++) {
            segs[e] = off;
            off += ((g_counts[e] + 127) >> 7) << 7;
        }
    }
    if (b == 0 && tid == 0) {
        int nt = 0;
        for (int e = 0; e < NE; e++) {
            int t = (g_counts[e] + 127) >> 7;
            for (int m = 0; m < t; m++) {
                g_tile_expert[nt] = e;
                g_tile_row0[nt] = segs[e] + (m << 7);
                nt++;
            }
        }
        g_ntiles = nt;
    }

    int t = b * 256 + tid;
#pragma unroll
    for (int k = 0; k < 2; k++) {
        int e = g_tok_e[2 * t + k];
        int row = segs[e] + atomicAdd(&g_fill[e], 1);
        g_row_token[row] = t;
        g_row_coef[row] = g_tok_p[2 * t + k];
        g_token_row[2 * t + k] = row;
    }
}

// ---------------- gather: full-width fp16 X copy (one block per row) ----------------
__global__ void k_gather(const float* __restrict__ x) {
    int row = blockIdx.x;
    int t = g_row_token[row];
    if (t < 0) return;  // padded rows already zeroed by k_prep
    size_t off = (size_t)row * DIM + threadIdx.x * 4;
    float4 v = *(const float4*)(x + (size_t)t * DIM + threadIdx.x * 4);
    *(uint2*)(g_Xhi + off) = make_uint2(pk(f2h(v.x), f2h(v.y)), pk(f2h(v.z), f2h(v.w)));
}

// ---------------- GEMM13: H = relu(X W1^T)^2 * (X W3^T) ----------------
// CTA 128x128, 512 threads (16 warps), warp tile 32x32, BK=32, 4-stage.
#define RS 80
#define S13_A  0
#define S13_B1 10240
#define S13_B3 20480
#define SS13 30720
#define SMEM13 (4 * SS13)

__device__ __forceinline__ void load13(u32 sbase, int stage, int kt,
                                       const u16* Ah, size_t wbase, int tid) {
    int k0 = kt * 32;
    u32 st = sbase + stage * SS13;
#pragma unroll
    for (int it = 0; it < 3; it++) {
        int c = tid + it * 512;
        int r = (c >> 2) & 127, ch = c & 3;
        u32 dst; const u16* src;
        if (c < 512)       { dst = st + S13_A + r * RS + ch * 16; src = Ah + (size_t)r * DIM + k0 + ch * 8; }
        else if (c < 1024) { dst = st + S13_B1 + r * RS + ch * 16; src = g_W1hi + (wbase + r) * DIM + k0 + ch * 8; }
        else               { dst = st + S13_B3 + r * RS + ch * 16; src = g_W3hi + (wbase + r) * DIM + k0 + ch * 8; }
        cpa16(dst, src);
    }
}

__global__ __launch_bounds__(512, 1)
void k_gemm13() {
    if ((int)blockIdx.x >= g_ntiles) return;
    extern __shared__ char smraw[];
    u32 sbase = smem_u32(smraw);
    int tid = threadIdx.x, wid = tid >> 5, lane = tid & 31;
    int warpM = wid >> 2, warpN = wid & 3;
    int e = g_tile_expert[blockIdx.x], row0 = g_tile_row0[blockIdx.x];
    int n0w = blockIdx.y * 128;

    const u16* Ah = g_Xhi + (size_t)row0 * DIM;
    size_t wbase = (size_t)e * HID + n0w;

    u32 aoff = (u32)((lane & 15) * RS + (lane >> 4) * 16);
    u32 b4off = (u32)(((lane & 7) + ((lane >> 4) << 3)) * RS + ((lane >> 3) & 1) * 16);
    u32 aW = (u32)(warpM * 32 * RS);
    u32 bW = (u32)(warpN * 32 * RS);

    float acc1[2][4][4], acc3[2][4][4];
#pragma unroll
    for (int mt = 0; mt < 2; mt++)
#pragma unroll
        for (int nt = 0; nt < 4; nt++)
#pragma unroll
            for (int j = 0; j < 4; j++) { acc1[mt][nt][j] = 0.f; acc3[mt][nt][j] = 0.f; }

    const int KT = DIM / 32;
    load13(sbase, 0, 0, Ah, wbase, tid); cpa_commit();
    load13(sbase, 1, 1, Ah, wbase, tid); cpa_commit();
    load13(sbase, 2, 2, Ah, wbase, tid); cpa_commit();

    for (int kt = 0; kt < KT; kt++) {
        cpa_wait2();
        __syncthreads();
        if (kt + 3 < KT) load13(sbase, (kt + 3) & 3, kt + 3, Ah, wbase, tid);
        cpa_commit();
        u32 st = sbase + (kt & 3) * SS13;
#pragma unroll
        for (int kh = 0; kh < 2; kh++) {
            u32 AH[2][4];
#pragma unroll
            for (int mt = 0; mt < 2; mt++)
                ldsm4(AH[mt], st + S13_A + aW + mt * 16 * RS + kh * 32 + aoff);
#pragma unroll
            for (int ntp = 0; ntp < 2; ntp++) {
                u32 nb = bW + ntp * 16 * RS + kh * 32 + b4off;
                u32 b1[4], b3[4];
                ldsm4(b1, st + S13_B1 + nb);
                ldsm4(b3, st + S13_B3 + nb);
#pragma unroll
                for (int sub = 0; sub < 2; sub++)
#pragma unroll
                    for (int mt = 0; mt < 2; mt++) {
                        mma16816(acc1[mt][ntp * 2 + sub], AH[mt], b1 + sub * 2);
                        mma16816(acc3[mt][ntp * 2 + sub], AH[mt], b3 + sub * 2);
                    }
            }
        }
    }

    int g4 = lane >> 2, t4 = lane & 3;
#pragma unroll
    for (int mt = 0; mt < 2; mt++) {
        int rA = row0 + warpM * 32 + mt * 16 + g4;
#pragma unroll
        for (int nt = 0; nt < 4; nt++) {
            int col = n0w + warpN * 32 + nt * 8 + t4 * 2;
            const float* d1 = acc1[mt][nt];
            const float* d3 = acc3[mt][nt];
#pragma unroll
            for (int half = 0; half < 2; half++) {
                int row = rA + half * 8;
                float r0 = fmaxf(d1[half * 2], 0.f), r1 = fmaxf(d1[half * 2 + 1], 0.f);
                float h0 = r0 * r0 * d3[half * 2];
                float h1 = r1 * r1 * d3[half * 2 + 1];
                *(u32*)(g_Hhi + (size_t)row * HID + col) = pk(f2h(h0), f2h(h1));
            }
        }
    }
}

// ---------------- GEMM2: Orows = coef * (H W2^T) ----------------
#define S2_A 0
#define S2_B 10240
#define SS2 20480
#define SMEM2 (4 * SS2)

__device__ __forceinline__ void load2(u32 sbase, int stage, int kt,
                                      const u16* Ah, size_t wbase, int tid) {
    int k0 = kt * 32;
    u32 st = sbase + stage * SS2;
#pragma unroll
    for (int it = 0; it < 2; it++) {
        int c = tid + it * 512;
        int r = (c >> 2) & 127, ch = c & 3;
        u32 dst; const u16* src;
        if (c < 512) { dst = st + S2_A + r * RS + ch * 16; src = Ah + (size_t)r * HID + k0 + ch * 8; }
        else         { dst = st + S2_B + r * RS + ch * 16; src = g_W2hi + (wbase + r) * HID + k0 + ch * 8; }
        cpa16(dst, src);
    }
}

__global__ __launch_bounds__(512, 1)
void k_gemm2() {
    if ((int)blockIdx.x >= g_ntiles) return;
    extern __shared__ char smraw[];
    u32 sbase = smem_u32(smraw);
    int tid = threadIdx.x, wid = tid >> 5, lane = tid & 31;
    int warpM = wid >> 2, warpN = wid & 3;
    int e = g_tile_expert[blockIdx.x], row0 = g_tile_row0[blockIdx.x];
    int n0w = blockIdx.y * 128;

    const u16* Ah = g_Hhi + (size_t)row0 * HID;
    size_t wbase = (size_t)e * DIM + n0w;

    u32 aoff = (u32)((lane & 15) * RS + (lane >> 4) * 16);
    u32 b4off = (u32)(((lane & 7) + ((lane >> 4) << 3)) * RS + ((lane >> 3) & 1) * 16);
    u32 aW = (u32)(warpM * 32 * RS);
    u32 bW = (u32)(warpN * 32 * RS);

    float acc[2][4][4];
#pragma unroll
    for (int mt = 0; mt < 2; mt++)
#pragma unroll
        for (int nt = 0; nt < 4; nt++)
#pragma unroll
            for (int j = 0; j < 4; j++) acc[mt][nt][j] = 0.f;

    const int KT = HID / 32;
    load2(sbase, 0, 0, Ah, wbase, tid); cpa_commit();
    load2(sbase, 1, 1, Ah, wbase, tid); cpa_commit();
    load2(sbase, 2, 2, Ah, wbase, tid); cpa_commit();

    for (int kt = 0; kt < KT; kt++) {
        cpa_wait2();
        __syncthreads();
        if (kt + 3 < KT) load2(sbase, (kt + 3) & 3, kt + 3, Ah, wbase, tid);
        cpa_commit();
        u32 st = sbase + (kt & 3) * SS2;
#pragma unroll
        for (int kh = 0; kh < 2; kh++) {
            u32 AH[2][4];
#pragma unroll
            for (int mt = 0; mt < 2; mt++)
                ldsm4(AH[mt], st + S2_A + aW + mt * 16 * RS + kh * 32 + aoff);
#pragma unroll
            for (int ntp = 0; ntp < 2; ntp++) {
                u32 bh[4];
                ldsm4(bh, st + S2_B + bW + ntp * 16 * RS + kh * 32 + b4off);
#pragma unroll
                for (int sub = 0; sub < 2; sub++)
#pragma unroll
                    for (int mt = 0; mt < 2; mt++)
                        mma16816(acc[mt][ntp * 2 + sub], AH[mt], bh + sub * 2);
            }
        }
    }

    int g4 = lane >> 2, t4 = lane & 3;
#pragma unroll
    for (int mt = 0; mt < 2; mt++) {
        int rA = row0 + warpM * 32 + mt * 16 + g4;
        float c0 = g_row_coef[rA], c1 = g_row_coef[rA + 8];
#pragma unroll
        for (int nt = 0; nt < 4; nt++) {
            int col = n0w + warpN * 32 + nt * 8 + t4 * 2;
            const float* d = acc[mt][nt];
            *(float2*)(g_Orows + (size_t)rA * DIM + col) = make_float2(c0 * d[0], c0 * d[1]);
            *(float2*)(g_Orows + (size_t)(rA + 8) * DIM + col) = make_float2(c1 * d[2], c1 * d[3]);
        }
    }
}

__global__ void k_combine(float* __restrict__ out) {
    int t = blockIdx.x;
    int i = threadIdx.x * 4;
    int r0 = g_token_row[2 * t], r1 = g_token_row[2 * t + 1];
    float4 a = *(const float4*)(g_Orows + (size_t)r0 * DIM + i);
    float4 b = *(const float4*)(g_Orows + (size_t)r1 * DIM + i);
    *(float4*)(out + (size_t)t * DIM + i) =
        make_float4(a.x + b.x, a.y + b.y, a.z + b.z, a.w + b.w);
}

extern "C" void kernel_launch(void* const* d_in, const int* in_sizes, int n_in,
                              void* d_out, int out_size) {
    const float* x  = (const float*)d_in[0];
    const float* W1 = (const float*)d_in[1];
    const float* W2 = (const float*)d_in[2];
    const float* W3 = (const float*)d_in[3];
    const float* gw = (const float*)d_in[4];
    const float* gb = (const float*)d_in[5];
    float* out = (float*)d_out;

    cudaFuncSetAttribute(k_gemm13, cudaFuncAttributeMaxDynamicSharedMemorySize, SMEM13);
    cudaFuncSetAttribute(k_gemm2,  cudaFuncAttributeMaxDynamicSharedMemorySize, SMEM2);

    k_prep<<<57856, 256>>>(W1, W2, W3);
    k_gate<<<1024, 256>>>(x, gw, gb);
    k_route<<<32, 256>>>();
    k_gather<<<MAXROWS, 256>>>(x);
    k_gemm13<<<dim3(MAXMT, HID / 128), 512, SMEM13>>>();
    k_gemm2<<<dim3(MAXMT, DIM / 128), 512, SMEM2>>>();
    k_combine<<<NTOK, 256>>>(out);
}

// round 13
// speedup vs baseline: 1.0910x; 1.0405x over previous
#include <cuda_runtime.h>
#include <cuda_fp16.h>
#include <cstdint>

typedef unsigned short u16;
typedef unsigned int   u32;
typedef unsigned long long u64;

#define NTOK 8192
#define DIM  1024
#define HID  2048
#define NE   8
#define MAXROWS 17408
#define MAXMT 136

__device__ int   g_counts[NE], g_fill[NE], g_ntiles;
__device__ int   g_tile_expert[MAXMT], g_tile_row0[MAXMT];
__device__ int   g_row_token[MAXROWS];
__device__ float g_row_coef[MAXROWS];
__device__ int   g_token_row[NTOK * 2];
__device__ int   g_tok_e[NTOK * 2];
__device__ float g_tok_p[NTOK * 2];

__device__ __align__(16) u16 g_Xhi[(size_t)MAXROWS * DIM];
__device__ __align__(16) u16 g_W1hi[(size_t)NE * HID * DIM];
__device__ __align__(16) u16 g_W3hi[(size_t)NE * HID * DIM];
__device__ __align__(16) u16 g_W2hi[(size_t)NE * DIM * HID];
__device__ __align__(16) u16 g_Hhi[(size_t)MAXROWS * HID];
__device__ __align__(16) float g_Orows[(size_t)MAXROWS * DIM];

__device__ __forceinline__ u16 f2h(float f) { return __half_as_ushort(__float2half_rn(f)); }
__device__ __forceinline__ u32 pk(u16 a, u16 b) { return (u32)a | ((u32)b << 16); }

__device__ __forceinline__ u32 smem_u32(const void* p) {
    u32 a;
    asm("{ .reg .u64 t; cvta.to.shared.u64 t, %1; cvt.u32.u64 %0, t; }" : "=r"(a) : "l"(p));
    return a;
}
__device__ __forceinline__ void cpa16(u32 dst, const void* src) {
    asm volatile("cp.async.cg.shared.global [%0], [%1], 16;" :: "r"(dst), "l"(src) : "memory");
}
__device__ __forceinline__ void cpa_commit() { asm volatile("cp.async.commit_group;" ::: "memory"); }
__device__ __forceinline__ void cpa_wait2() { asm volatile("cp.async.wait_group 2;" ::: "memory"); }

__device__ __forceinline__ void ldsm4(u32* r, u32 addr) {
    asm volatile("ldmatrix.sync.aligned.m8n8.x4.shared.b16 {%0,%1,%2,%3}, [%4];"
                 : "=r"(r[0]), "=r"(r[1]), "=r"(r[2]), "=r"(r[3]) : "r"(addr));
}
__device__ __forceinline__ void mma16816(float* c, const u32* a, const u32* b) {
    asm volatile(
        "mma.sync.aligned.m16n8k16.row.col.f32.f16.f16.f32 "
        "{%0,%1,%2,%3}, {%4,%5,%6,%7}, {%8,%9}, {%0,%1,%2,%3};"
        : "+f"(c[0]), "+f"(c[1]), "+f"(c[2]), "+f"(c[3])
        : "r"(a[0]), "r"(a[1]), "r"(a[2]), "r"(a[3]), "r"(b[0]), "r"(b[1]));
}

// ---------------- tiny init (must precede gate's count atomics) ----------------
__global__ void k_init() {
    int i = blockIdx.x * 256 + threadIdx.x;
    if (i < MAXROWS) { g_row_token[i] = -1; g_row_coef[i] = 0.f; }
    if (i < NE) { g_counts[i] = 0; g_fill[i] = 0; }
}

// ---------------- prep+gate fused: weight fp16 conversion + zero Xhi + gate ----
// blocks [0,49152) weights ; [49152,57856) zero Xhi ; [57856,58880) gate
__global__ void k_prep(const float* __restrict__ x, const float* __restrict__ gw,
                       const float* __restrict__ gb,
                       const float* __restrict__ W1, const float* __restrict__ W2,
                       const float* __restrict__ W3) {
    int b = blockIdx.x;
    if (b < 49152) {
        int which = b >> 14;
        size_t i = ((size_t)(b & 16383) * 256 + threadIdx.x) * 4;
        const float* src = (which == 0) ? W1 : (which == 1) ? W3 : W2;
        u16* dst = (which == 0) ? g_W1hi : (which == 1) ? g_W3hi : g_W2hi;
        float4 v = *(const float4*)(src + i);
        *(uint2*)(dst + i) = make_uint2(pk(f2h(v.x), f2h(v.y)), pk(f2h(v.z), f2h(v.w)));
    } else if (b < 57856) {
        size_t i = ((size_t)(b - 49152) * 256 + threadIdx.x) * 8;
        *(uint4*)(g_Xhi + i) = make_uint4(0, 0, 0, 0);
    } else {
        int w = (b - 57856) * 8 + (threadIdx.x >> 5);
        int lane = threadIdx.x & 31;
        const float* xr = x + (size_t)w * DIM;
        float acc[NE];
#pragma unroll
        for (int e = 0; e < NE; e++) acc[e] = 0.f;
        for (int j = lane; j < DIM; j += 32) {
            float xv = xr[j];
#pragma unroll
            for (int e = 0; e < NE; e++) acc[e] = fmaf(xv, gw[e * DIM + j], acc[e]);
        }
#pragma unroll
        for (int e = 0; e < NE; e++)
#pragma unroll
            for (int o = 16; o; o >>= 1) acc[e] += __shfl_xor_sync(0xffffffffu, acc[e], o);
        if (lane == 0) {
#pragma unroll
            for (int e = 0; e < NE; e++) acc[e] += gb[e];
            int e0 = 0;
#pragma unroll
            for (int e = 1; e < NE; e++) if (acc[e] > acc[e0]) e0 = e;
            int e1 = (e0 == 0) ? 1 : 0;
#pragma unroll
            for (int e = 0; e < NE; e++) if (e != e0 && acc[e] > acc[e1]) e1 = e;
            float p0 = 1.f / (1.f + expf(acc[e1] - acc[e0]));
            g_tok_e[2 * w] = e0; g_tok_e[2 * w + 1] = e1;
            g_tok_p[2 * w] = p0; g_tok_p[2 * w + 1] = 1.f - p0;
            atomicAdd(&g_counts[e0], 1);
            atomicAdd(&g_counts[e1], 1);
        }
    }
}

// ---------------- route: offsets + assign (32 blocks) ----------------
__global__ void k_route() {
    int b = blockIdx.x, tid = threadIdx.x;

    int segs[NE];
    {
        int off = 0;
#pragma unroll
        for (int e = 0; e < NE; e++) {
            segs[e] = off;
            off += ((g_counts[e] + 127) >> 7) << 7;
        }
    }
    if (b == 0 && tid == 0) {
        int nt = 0;
        for (int e = 0; e < NE; e++) {
            int t = (g_counts[e] + 127) >> 7;
            for (int m = 0; m < t; m++) {
                g_tile_expert[nt] = e;
                g_tile_row0[nt] = segs[e] + (m << 7);
                nt++;
            }
        }
        g_ntiles = nt;
    }

    int t = b * 256 + tid;
#pragma unroll
    for (int k = 0; k < 2; k++) {
        int e = g_tok_e[2 * t + k];
        int row = segs[e] + atomicAdd(&g_fill[e], 1);
        g_row_token[row] = t;
        g_row_coef[row] = g_tok_p[2 * t + k];
        g_token_row[2 * t + k] = row;
    }
}

// ---------------- gather: full-width fp16 X copy (one block per row) ----------------
__global__ void k_gather(const float* __restrict__ x) {
    int row = blockIdx.x;
    int t = g_row_token[row];
    if (t < 0) return;  // padded rows already zeroed by k_prep
    size_t off = (size_t)row * DIM + threadIdx.x * 4;
    float4 v = *(const float4*)(x + (size_t)t * DIM + threadIdx.x * 4);
    *(uint2*)(g_Xhi + off) = make_uint2(pk(f2h(v.x), f2h(v.y)), pk(f2h(v.z), f2h(v.w)));
}

// ---------------- GEMM13: H = relu(X W1^T)^2 * (X W3^T) ----------------
// CTA 128x128, 512 threads (16 warps), warp tile 32x32, BK=32, 4-stage.
#define RS 80
#define S13_A  0
#define S13_B1 10240
#define S13_B3 20480
#define SS13 30720
#define SMEM13 (4 * SS13)

__device__ __forceinline__ void load13(u32 sbase, int stage, int kt,
                                       const u16* Ah, size_t wbase, int tid) {
    int k0 = kt * 32;
    u32 st = sbase + stage * SS13;
#pragma unroll
    for (int it = 0; it < 3; it++) {
        int c = tid + it * 512;
        int r = (c >> 2) & 127, ch = c & 3;
        u32 dst; const u16* src;
        if (c < 512)       { dst = st + S13_A + r * RS + ch * 16; src = Ah + (size_t)r * DIM + k0 + ch * 8; }
        else if (c < 1024) { dst = st + S13_B1 + r * RS + ch * 16; src = g_W1hi + (wbase + r) * DIM + k0 + ch * 8; }
        else               { dst = st + S13_B3 + r * RS + ch * 16; src = g_W3hi + (wbase + r) * DIM + k0 + ch * 8; }
        cpa16(dst, src);
    }
}

__global__ __launch_bounds__(512, 1)
void k_gemm13() {
    if ((int)blockIdx.x >= g_ntiles) return;
    extern __shared__ char smraw[];
    u32 sbase = smem_u32(smraw);
    int tid = threadIdx.x, wid = tid >> 5, lane = tid & 31;
    int warpM = wid >> 2, warpN = wid & 3;
    int e = g_tile_expert[blockIdx.x], row0 = g_tile_row0[blockIdx.x];
    int n0w = blockIdx.y * 128;

    const u16* Ah = g_Xhi + (size_t)row0 * DIM;
    size_t wbase = (size_t)e * HID + n0w;

    u32 aoff = (u32)((lane & 15) * RS + (lane >> 4) * 16);
    u32 b4off = (u32)(((lane & 7) + ((lane >> 4) << 3)) * RS + ((lane >> 3) & 1) * 16);
    u32 aW = (u32)(warpM * 32 * RS);
    u32 bW = (u32)(warpN * 32 * RS);

    float acc1[2][4][4], acc3[2][4][4];
#pragma unroll
    for (int mt = 0; mt < 2; mt++)
#pragma unroll
        for (int nt = 0; nt < 4; nt++)
#pragma unroll
            for (int j = 0; j < 4; j++) { acc1[mt][nt][j] = 0.f; acc3[mt][nt][j] = 0.f; }

    const int KT = DIM / 32;
    load13(sbase, 0, 0, Ah, wbase, tid); cpa_commit();
    load13(sbase, 1, 1, Ah, wbase, tid); cpa_commit();
    load13(sbase, 2, 2, Ah, wbase, tid); cpa_commit();

    for (int kt = 0; kt < KT; kt++) {
        cpa_wait2();
        __syncthreads();
        if (kt + 3 < KT) load13(sbase, (kt + 3) & 3, kt + 3, Ah, wbase, tid);
        cpa_commit();
        u32 st = sbase + (kt & 3) * SS13;
#pragma unroll
        for (int kh = 0; kh < 2; kh++) {
            u32 AH[2][4];
#pragma unroll
            for (int mt = 0; mt < 2; mt++)
                ldsm4(AH[mt], st + S13_A + aW + mt * 16 * RS + kh * 32 + aoff);
#pragma unroll
            for (int ntp = 0; ntp < 2; ntp++) {
                u32 nb = bW + ntp * 16 * RS + kh * 32 + b4off;
                u32 b1[4], b3[4];
                ldsm4(b1, st + S13_B1 + nb);
                ldsm4(b3, st + S13_B3 + nb);
#pragma unroll
                for (int sub = 0; sub < 2; sub++)
#pragma unroll
                    for (int mt = 0; mt < 2; mt++) {
                        mma16816(acc1[mt][ntp * 2 + sub], AH[mt], b1 + sub * 2);
                        mma16816(acc3[mt][ntp * 2 + sub], AH[mt], b3 + sub * 2);
                    }
            }
        }
    }

    int g4 = lane >> 2, t4 = lane & 3;
#pragma unroll
    for (int mt = 0; mt < 2; mt++) {
        int rA = row0 + warpM * 32 + mt * 16 + g4;
#pragma unroll
        for (int nt = 0; nt < 4; nt++) {
            int col = n0w + warpN * 32 + nt * 8 + t4 * 2;
            const float* d1 = acc1[mt][nt];
            const float* d3 = acc3[mt][nt];
#pragma unroll
            for (int half = 0; half < 2; half++) {
                int row = rA + half * 8;
                float r0 = fmaxf(d1[half * 2], 0.f), r1 = fmaxf(d1[half * 2 + 1], 0.f);
                float h0 = r0 * r0 * d3[half * 2];
                float h1 = r1 * r1 * d3[half * 2 + 1];
                *(u32*)(g_Hhi + (size_t)row * HID + col) = pk(f2h(h0), f2h(h1));
            }
        }
    }
}

// ---------------- GEMM2: Orows = coef * (H W2^T) ----------------
// CTA 128x128, 512 threads, warp tile 32x32, BK=32, 4-stage, 2 CTAs/SM.
#define S2_A 0
#define S2_B 10240
#define SS2 20480
#define SMEM2 (4 * SS2)

__device__ __forceinline__ void load2(u32 sbase, int stage, int kt,
                                      const u16* Ah, size_t wbase, int tid) {
    int k0 = kt * 32;
    u32 st = sbase + stage * SS2;
#pragma unroll
    for (int it = 0; it < 2; it++) {
        int c = tid + it * 512;
        int r = (c >> 2) & 127, ch = c & 3;
        u32 dst; const u16* src;
        if (c < 512) { dst = st + S2_A + r * RS + ch * 16; src = Ah + (size_t)r * HID + k0 + ch * 8; }
        else         { dst = st + S2_B + r * RS + ch * 16; src = g_W2hi + (wbase + r) * HID + k0 + ch * 8; }
        cpa16(dst, src);
    }
}

__global__ __launch_bounds__(512, 2)
void k_gemm2() {
    if ((int)blockIdx.x >= g_ntiles) return;
    extern __shared__ char smraw[];
    u32 sbase = smem_u32(smraw);
    int tid = threadIdx.x, wid = tid >> 5, lane = tid & 31;
    int warpM = wid >> 2, warpN = wid & 3;
    int e = g_tile_expert[blockIdx.x], row0 = g_tile_row0[blockIdx.x];
    int n0w = blockIdx.y * 128;

    const u16* Ah = g_Hhi + (size_t)row0 * HID;
    size_t wbase = (size_t)e * DIM + n0w;

    u32 aoff = (u32)((lane & 15) * RS + (lane >> 4) * 16);
    u32 b4off = (u32)(((lane & 7) + ((lane >> 4) << 3)) * RS + ((lane >> 3) & 1) * 16);
    u32 aW = (u32)(warpM * 32 * RS);
    u32 bW = (u32)(warpN * 32 * RS);

    float acc[2][4][4];
#pragma unroll
    for (int mt = 0; mt < 2; mt++)
#pragma unroll
        for (int nt = 0; nt < 4; nt++)
#pragma unroll
            for (int j = 0; j < 4; j++) acc[mt][nt][j] = 0.f;

    const int KT = HID / 32;
    load2(sbase, 0, 0, Ah, wbase, tid); cpa_commit();
    load2(sbase, 1, 1, Ah, wbase, tid); cpa_commit();
    load2(sbase, 2, 2, Ah, wbase, tid); cpa_commit();

    for (int kt = 0; kt < KT; kt++) {
        cpa_wait2();
        __syncthreads();
        if (kt + 3 < KT) load2(sbase, (kt + 3) & 3, kt + 3, Ah, wbase, tid);
        cpa_commit();
        u32 st = sbase + (kt & 3) * SS2;
#pragma unroll
        for (int kh = 0; kh < 2; kh++) {
            u32 AH[2][4];
#pragma unroll
            for (int mt = 0; mt < 2; mt++)
                ldsm4(AH[mt], st + S2_A + aW + mt * 16 * RS + kh * 32 + aoff);
#pragma unroll
            for (int ntp = 0; ntp < 2; ntp++) {
                u32 bh[4];
                ldsm4(bh, st + S2_B + bW + ntp * 16 * RS + kh * 32 + b4off);
#pragma unroll
                for (int sub = 0; sub < 2; sub++)
#pragma unroll
                    for (int mt = 0; mt < 2; mt++)
                        mma16816(acc[mt][ntp * 2 + sub], AH[mt], bh + sub * 2);
            }
        }
    }

    int g4 = lane >> 2, t4 = lane & 3;
#pragma unroll
    for (int mt = 0; mt < 2; mt++) {
        int rA = row0 + warpM * 32 + mt * 16 + g4;
        float c0 = g_row_coef[rA], c1 = g_row_coef[rA + 8];
#pragma unroll
        for (int nt = 0; nt < 4; nt++) {
            int col = n0w + warpN * 32 + nt * 8 + t4 * 2;
            const float* d = acc[mt][nt];
            *(float2*)(g_Orows + (size_t)rA * DIM + col) = make_float2(c0 * d[0], c0 * d[1]);
            *(float2*)(g_Orows + (size_t)(rA + 8) * DIM + col) = make_float2(c1 * d[2], c1 * d[3]);
        }
    }
}

__global__ void k_combine(float* __restrict__ out) {
    int t = blockIdx.x;
    int i = threadIdx.x * 4;
    int r0 = g_token_row[2 * t], r1 = g_token_row[2 * t + 1];
    float4 a = *(const float4*)(g_Orows + (size_t)r0 * DIM + i);
    float4 b = *(const float4*)(g_Orows + (size_t)r1 * DIM + i);
    *(float4*)(out + (size_t)t * DIM + i) =
        make_float4(a.x + b.x, a.y + b.y, a.z + b.z, a.w + b.w);
}

extern "C" void kernel_launch(void* const* d_in, const int* in_sizes, int n_in,
                              void* d_out, int out_size) {
    const float* x  = (const float*)d_in[0];
    const float* W1 = (const float*)d_in[1];
    const float* W2 = (const float*)d_in[2];
    const float* W3 = (const float*)d_in[3];
    const float* gw = (const float*)d_in[4];
    const float* gb = (const float*)d_in[5];
    float* out = (float*)d_out;

    cudaFuncSetAttribute(k_gemm13, cudaFuncAttributeMaxDynamicSharedMemorySize, SMEM13);
    cudaFuncSetAttribute(k_gemm2,  cudaFuncAttributeMaxDynamicSharedMemorySize, SMEM2);

    k_init<<<68, 256>>>();
    k_prep<<<58880, 256>>>(x, gw, gb, W1, W2, W3);
    k_route<<<32, 256>>>();
    k_gather<<<MAXROWS, 256>>>(x);
    k_gemm13<<<dim3(MAXMT, HID / 128), 512, SMEM13>>>();
    k_gemm2<<<dim3(MAXMT, DIM / 128), 512, SMEM2>>>();
    k_combine<<<NTOK, 256>>>(out);
}

// round 14
// speedup vs baseline: 1.0958x; 1.0045x over previous
#include <cuda_runtime.h>
#include <cuda_fp16.h>
#include <cstdint>

typedef unsigned short u16;
typedef unsigned int   u32;
typedef unsigned long long u64;

#define NTOK 8192
#define DIM  1024
#define HID  2048
#define NE   8
#define MAXROWS 17408
#define MAXMT 136

__device__ int   g_counts[NE], g_fill[NE], g_ntiles;
__device__ int   g_tile_expert[MAXMT], g_tile_row0[MAXMT];
__device__ int   g_row_token[MAXROWS];
__device__ float g_row_coef[MAXROWS];
__device__ int   g_token_row[NTOK * 2];
__device__ int   g_tok_e[NTOK * 2];
__device__ float g_tok_p[NTOK * 2];

__device__ __align__(16) u16 g_Xhi[(size_t)MAXROWS * DIM];
__device__ __align__(16) u16 g_W1hi[(size_t)NE * HID * DIM];
__device__ __align__(16) u16 g_W3hi[(size_t)NE * HID * DIM];
__device__ __align__(16) u16 g_W2hi[(size_t)NE * DIM * HID];
__device__ __align__(16) u16 g_Hhi[(size_t)MAXROWS * HID];
__device__ __align__(16) float g_Orows[(size_t)MAXROWS * DIM];

__device__ __forceinline__ u16 f2h(float f) { return __half_as_ushort(__float2half_rn(f)); }
__device__ __forceinline__ float h2f(u16 u) { return __half2float(__ushort_as_half(u)); }
__device__ __forceinline__ u32 pk(u16 a, u16 b) { return (u32)a | ((u32)b << 16); }

__device__ __forceinline__ u32 smem_u32(const void* p) {
    u32 a;
    asm("{ .reg .u64 t; cvta.to.shared.u64 t, %1; cvt.u32.u64 %0, t; }" : "=r"(a) : "l"(p));
    return a;
}
__device__ __forceinline__ void cpa16(u32 dst, const void* src) {
    asm volatile("cp.async.cg.shared.global [%0], [%1], 16;" :: "r"(dst), "l"(src) : "memory");
}
__device__ __forceinline__ void cpa_commit() { asm volatile("cp.async.commit_group;" ::: "memory"); }
__device__ __forceinline__ void cpa_wait2() { asm volatile("cp.async.wait_group 2;" ::: "memory"); }

__device__ __forceinline__ void ldsm4(u32* r, u32 addr) {
    asm volatile("ldmatrix.sync.aligned.m8n8.x4.shared.b16 {%0,%1,%2,%3}, [%4];"
                 : "=r"(r[0]), "=r"(r[1]), "=r"(r[2]), "=r"(r[3]) : "r"(addr));
}
__device__ __forceinline__ void mma16816(float* c, const u32* a, const u32* b) {
    asm volatile(
        "mma.sync.aligned.m16n8k16.row.col.f32.f16.f16.f32 "
        "{%0,%1,%2,%3}, {%4,%5,%6,%7}, {%8,%9}, {%0,%1,%2,%3};"
        : "+f"(c[0]), "+f"(c[1]), "+f"(c[2]), "+f"(c[3])
        : "r"(a[0]), "r"(a[1]), "r"(a[2]), "r"(a[3]), "r"(b[0]), "r"(b[1]));
}

// ---------------- init (main stream; precedes gate atomics + gather reads) ----
__global__ void k_init() {
    int i = blockIdx.x * 256 + threadIdx.x;
    if (i < MAXROWS) { g_row_token[i] = -1; g_row_coef[i] = 0.f; }
    if (i < NE) { g_counts[i] = 0; g_fill[i] = 0; }
}

// ---------------- prepw: weight fp16 conversion only (side stream) ----------
__global__ void k_prepw(const float* __restrict__ W1, const float* __restrict__ W2,
                        const float* __restrict__ W3) {
    int b = blockIdx.x;
    int which = b >> 14;
    size_t i = ((size_t)(b & 16383) * 256 + threadIdx.x) * 4;
    const float* src = (which == 0) ? W1 : (which == 1) ? W3 : W2;
    u16* dst = (which == 0) ? g_W1hi : (which == 1) ? g_W3hi : g_W2hi;
    float4 v = *(const float4*)(src + i);
    *(uint2*)(dst + i) = make_uint2(pk(f2h(v.x), f2h(v.y)), pk(f2h(v.z), f2h(v.w)));
}

__global__ void k_gate(const float* __restrict__ x, const float* __restrict__ gw,
                       const float* __restrict__ gb) {
    int w = (blockIdx.x * blockDim.x + threadIdx.x) >> 5;
    int lane = threadIdx.x & 31;
    if (w >= NTOK) return;
    const float* xr = x + (size_t)w * DIM;
    float acc[NE];
#pragma unroll
    for (int e = 0; e < NE; e++) acc[e] = 0.f;
    for (int j = lane; j < DIM; j += 32) {
        float xv = xr[j];
#pragma unroll
        for (int e = 0; e < NE; e++) acc[e] = fmaf(xv, gw[e * DIM + j], acc[e]);
    }
#pragma unroll
    for (int e = 0; e < NE; e++)
#pragma unroll
        for (int o = 16; o; o >>= 1) acc[e] += __shfl_xor_sync(0xffffffffu, acc[e], o);
    if (lane == 0) {
#pragma unroll
        for (int e = 0; e < NE; e++) acc[e] += gb[e];
        int e0 = 0;
#pragma unroll
        for (int e = 1; e < NE; e++) if (acc[e] > acc[e0]) e0 = e;
        int e1 = (e0 == 0) ? 1 : 0;
#pragma unroll
        for (int e = 0; e < NE; e++) if (e != e0 && acc[e] > acc[e1]) e1 = e;
        float p0 = 1.f / (1.f + expf(acc[e1] - acc[e0]));
        g_tok_e[2 * w] = e0; g_tok_e[2 * w + 1] = e1;
        g_tok_p[2 * w] = p0; g_tok_p[2 * w + 1] = 1.f - p0;
        atomicAdd(&g_counts[e0], 1);
        atomicAdd(&g_counts[e1], 1);
    }
}

// ---------------- route: offsets + assign (32 blocks) ----------------
__global__ void k_route() {
    int b = blockIdx.x, tid = threadIdx.x;

    int segs[NE];
    {
        int off = 0;
#pragma unroll
        for (int e = 0; e < NE; e++) {
            segs[e] = off;
            off += ((g_counts[e] + 127) >> 7) << 7;
        }
    }
    if (b == 0 && tid == 0) {
        int nt = 0;
        for (int e = 0; e < NE; e++) {
            int t = (g_counts[e] + 127) >> 7;
            for (int m = 0; m < t; m++) {
                g_tile_expert[nt] = e;
                g_tile_row0[nt] = segs[e] + (m << 7);
                nt++;
            }
        }
        g_ntiles = nt;
    }

    int t = b * 256 + tid;
#pragma unroll
    for (int k = 0; k < 2; k++) {
        int e = g_tok_e[2 * t + k];
        int row = segs[e] + atomicAdd(&g_fill[e], 1);
        g_row_token[row] = t;
        g_row_coef[row] = g_tok_p[2 * t + k];
        g_token_row[2 * t + k] = row;
    }
}

// ---------------- gather: full-width fp16 X copy; zeros for padded rows ----
__global__ void k_gather(const float* __restrict__ x) {
    int row = blockIdx.x;
    int t = g_row_token[row];
    size_t off = (size_t)row * DIM + threadIdx.x * 4;
    float4 v = make_float4(0.f, 0.f, 0.f, 0.f);
    if (t >= 0) v = *(const float4*)(x + (size_t)t * DIM + threadIdx.x * 4);
    *(uint2*)(g_Xhi + off) = make_uint2(pk(f2h(v.x), f2h(v.y)), pk(f2h(v.z), f2h(v.w)));
}

// ---------------- GEMM13: H = relu(X W1^T)^2 * (X W3^T) ----------------
// CTA 128x128, 512 threads (16 warps), warp tile 32x32, BK=32, 4-stage.
#define RS 80
#define S13_A  0
#define S13_B1 10240
#define S13_B3 20480
#define SS13 30720
#define SMEM13 (4 * SS13)

__device__ __forceinline__ void load13(u32 sbase, int stage, int kt,
                                       const u16* Ah, size_t wbase, int tid) {
    int k0 = kt * 32;
    u32 st = sbase + stage * SS13;
#pragma unroll
    for (int it = 0; it < 3; it++) {
        int c = tid + it * 512;
        int r = (c >> 2) & 127, ch = c & 3;
        u32 dst; const u16* src;
        if (c < 512)       { dst = st + S13_A + r * RS + ch * 16; src = Ah + (size_t)r * DIM + k0 + ch * 8; }
        else if (c < 1024) { dst = st + S13_B1 + r * RS + ch * 16; src = g_W1hi + (wbase + r) * DIM + k0 + ch * 8; }
        else               { dst = st + S13_B3 + r * RS + ch * 16; src = g_W3hi + (wbase + r) * DIM + k0 + ch * 8; }
        cpa16(dst, src);
    }
}

__global__ __launch_bounds__(512, 1)
void k_gemm13() {
    if ((int)blockIdx.x >= g_ntiles) return;
    extern __shared__ char smraw[];
    u32 sbase = smem_u32(smraw);
    int tid = threadIdx.x, wid = tid >> 5, lane = tid & 31;
    int warpM = wid >> 2, warpN = wid & 3;
    int e = g_tile_expert[blockIdx.x], row0 = g_tile_row0[blockIdx.x];
    int n0w = blockIdx.y * 128;

    const u16* Ah = g_Xhi + (size_t)row0 * DIM;
    size_t wbase = (size_t)e * HID + n0w;

    u32 aoff = (u32)((lane & 15) * RS + (lane >> 4) * 16);
    u32 b4off = (u32)(((lane & 7) + ((lane >> 4) << 3)) * RS + ((lane >> 3) & 1) * 16);
    u32 aW = (u32)(warpM * 32 * RS);
    u32 bW = (u32)(warpN * 32 * RS);

    float acc1[2][4][4], acc3[2][4][4];
#pragma unroll
    for (int mt = 0; mt < 2; mt++)
#pragma unroll
        for (int nt = 0; nt < 4; nt++)
#pragma unroll
            for (int j = 0; j < 4; j++) { acc1[mt][nt][j] = 0.f; acc3[mt][nt][j] = 0.f; }

    const int KT = DIM / 32;
    load13(sbase, 0, 0, Ah, wbase, tid); cpa_commit();
    load13(sbase, 1, 1, Ah, wbase, tid); cpa_commit();
    load13(sbase, 2, 2, Ah, wbase, tid); cpa_commit();

    for (int kt = 0; kt < KT; kt++) {
        cpa_wait2();
        __syncthreads();
        if (kt + 3 < KT) load13(sbase, (kt + 3) & 3, kt + 3, Ah, wbase, tid);
        cpa_commit();
        u32 st = sbase + (kt & 3) * SS13;
#pragma unroll
        for (int kh = 0; kh < 2; kh++) {
            u32 AH[2][4];
#pragma unroll
            for (int mt = 0; mt < 2; mt++)
                ldsm4(AH[mt], st + S13_A + aW + mt * 16 * RS + kh * 32 + aoff);
#pragma unroll
            for (int ntp = 0; ntp < 2; ntp++) {
                u32 nb = bW + ntp * 16 * RS + kh * 32 + b4off;
                u32 b1[4], b3[4];
                ldsm4(b1, st + S13_B1 + nb);
                ldsm4(b3, st + S13_B3 + nb);
#pragma unroll
                for (int sub = 0; sub < 2; sub++)
#pragma unroll
                    for (int mt = 0; mt < 2; mt++) {
                        mma16816(acc1[mt][ntp * 2 + sub], AH[mt], b1 + sub * 2);
                        mma16816(acc3[mt][ntp * 2 + sub], AH[mt], b3 + sub * 2);
                    }
            }
        }
    }

    int g4 = lane >> 2, t4 = lane & 3;
#pragma unroll
    for (int mt = 0; mt < 2; mt++) {
        int rA = row0 + warpM * 32 + mt * 16 + g4;
#pragma unroll
        for (int nt = 0; nt < 4; nt++) {
            int col = n0w + warpN * 32 + nt * 8 + t4 * 2;
            const float* d1 = acc1[mt][nt];
            const float* d3 = acc3[mt][nt];
#pragma unroll
            for (int half = 0; half < 2; half++) {
                int row = rA + half * 8;
                float r0 = fmaxf(d1[half * 2], 0.f), r1 = fmaxf(d1[half * 2 + 1], 0.f);
                float h0 = r0 * r0 * d3[half * 2];
                float h1 = r1 * r1 * d3[half * 2 + 1];
                *(u32*)(g_Hhi + (size_t)row * HID + col) = pk(f2h(h0), f2h(h1));
            }
        }
    }
}

// ---------------- GEMM2: Orows = coef * (H W2^T) ----------------
// CTA 128x128, 512 threads, warp tile 32x32, BK=32, 4-stage, 2 CTAs/SM.
#define S2_A 0
#define S2_B 10240
#define SS2 20480
#define SMEM2 (4 * SS2)

__device__ __forceinline__ void load2(u32 sbase, int stage, int kt,
                                      const u16* Ah, size_t wbase, int tid) {
    int k0 = kt * 32;
    u32 st = sbase + stage * SS2;
#pragma unroll
    for (int it = 0; it < 2; it++) {
        int c = tid + it * 512;
        int r = (c >> 2) & 127, ch = c & 3;
        u32 dst; const u16* src;
        if (c < 512) { dst = st + S2_A + r * RS + ch * 16; src = Ah + (size_t)r * HID + k0 + ch * 8; }
        else         { dst = st + S2_B + r * RS + ch * 16; src = g_W2hi + (wbase + r) * HID + k0 + ch * 8; }
        cpa16(dst, src);
    }
}

__global__ __launch_bounds__(512, 2)
void k_gemm2() {
    if ((int)blockIdx.x >= g_ntiles) return;
    extern __shared__ char smraw[];
    u32 sbase = smem_u32(smraw);
    int tid = threadIdx.x, wid = tid >> 5, lane = tid & 31;
    int warpM = wid >> 2, warpN = wid & 3;
    int e = g_tile_expert[blockIdx.x], row0 = g_tile_row0[blockIdx.x];
    int n0w = blockIdx.y * 128;

    const u16* Ah = g_Hhi + (size_t)row0 * HID;
    size_t wbase = (size_t)e * DIM + n0w;

    u32 aoff = (u32)((lane & 15) * RS + (lane >> 4) * 16);
    u32 b4off = (u32)(((lane & 7) + ((lane >> 4) << 3)) * RS + ((lane >> 3) & 1) * 16);
    u32 aW = (u32)(warpM * 32 * RS);
    u32 bW = (u32)(warpN * 32 * RS);

    float acc[2][4][4];
#pragma unroll
    for (int mt = 0; mt < 2; mt++)
#pragma unroll
        for (int nt = 0; nt < 4; nt++)
#pragma unroll
            for (int j = 0; j < 4; j++) acc[mt][nt][j] = 0.f;

    const int KT = HID / 32;
    load2(sbase, 0, 0, Ah, wbase, tid); cpa_commit();
    load2(sbase, 1, 1, Ah, wbase, tid); cpa_commit();
    load2(sbase, 2, 2, Ah, wbase, tid); cpa_commit();

    for (int kt = 0; kt < KT; kt++) {
        cpa_wait2();
        __syncthreads();
        if (kt + 3 < KT) load2(sbase, (kt + 3) & 3, kt + 3, Ah, wbase, tid);
        cpa_commit();
        u32 st = sbase + (kt & 3) * SS2;
#pragma unroll
        for (int kh = 0; kh < 2; kh++) {
            u32 AH[2][4];
#pragma unroll
            for (int mt = 0; mt < 2; mt++)
                ldsm4(AH[mt], st + S2_A + aW + mt * 16 * RS + kh * 32 + aoff);
#pragma unroll
            for (int ntp = 0; ntp < 2; ntp++) {
                u32 bh[4];
                ldsm4(bh, st + S2_B + bW + ntp * 16 * RS + kh * 32 + b4off);
#pragma unroll
                for (int sub = 0; sub < 2; sub++)
#pragma unroll
                    for (int mt = 0; mt < 2; mt++)
                        mma16816(acc[mt][ntp * 2 + sub], AH[mt], bh + sub * 2);
            }
        }
    }

    int g4 = lane >> 2, t4 = lane & 3;
#pragma unroll
    for (int mt = 0; mt < 2; mt++) {
        int rA = row0 + warpM * 32 + mt * 16 + g4;
        float c0 = g_row_coef[rA], c1 = g_row_coef[rA + 8];
#pragma unroll
        for (int nt = 0; nt < 4; nt++) {
            int col = n0w + warpN * 32 + nt * 8 + t4 * 2;
            const float* d = acc[mt][nt];
            *(float2*)(g_Orows + (size_t)rA * DIM + col) = make_float2(c0 * d[0], c0 * d[1]);
            *(float2*)(g_Orows + (size_t)(rA + 8) * DIM + col) = make_float2(c1 * d[2], c1 * d[3]);
        }
    }
}

__global__ void k_combine(float* __restrict__ out) {
    int t = blockIdx.x;
    int i = threadIdx.x * 4;
    int r0 = g_token_row[2 * t], r1 = g_token_row[2 * t + 1];
    float4 a = *(const float4*)(g_Orows + (size_t)r0 * DIM + i);
    float4 b = *(const float4*)(g_Orows + (size_t)r1 * DIM + i);
    *(float4*)(out + (size_t)t * DIM + i) =
        make_float4(a.x + b.x, a.y + b.y, a.z + b.z, a.w + b.w);
}

extern "C" void kernel_launch(void* const* d_in, const int* in_sizes, int n_in,
                              void* d_out, int out_size) {
    const float* x  = (const float*)d_in[0];
    const float* W1 = (const float*)d_in[1];
    const float* W2 = (const float*)d_in[2];
    const float* W3 = (const float*)d_in[3];
    const float* gw = (const float*)d_in[4];
    const float* gb = (const float*)d_in[5];
    float* out = (float*)d_out;

    cudaFuncSetAttribute(k_gemm13, cudaFuncAttributeMaxDynamicSharedMemorySize, SMEM13);
    cudaFuncSetAttribute(k_gemm2,  cudaFuncAttributeMaxDynamicSharedMemorySize, SMEM2);

    // fork-join: weight conversion on a side stream, routing chain on main.
    cudaStream_t s1;
    cudaEvent_t evFork, evJoin;
    cudaStreamCreateWithFlags(&s1, cudaStreamNonBlocking);
    cudaEventCreateWithFlags(&evFork, cudaEventDisableTiming);
    cudaEventCreateWithFlags(&evJoin, cudaEventDisableTiming);

    cudaEventRecord(evFork, 0);
    cudaStreamWaitEvent(s1, evFork, 0);
    k_prepw<<<49152, 256, 0, s1>>>(W1, W2, W3);
    cudaEventRecord(evJoin, s1);

    k_init<<<68, 256>>>();
    k_gate<<<1024, 256>>>(x, gw, gb);
    k_route<<<32, 256>>>();
    k_gather<<<MAXROWS, 256>>>(x);

    cudaStreamWaitEvent(0, evJoin, 0);
    k_gemm13<<<dim3(MAXMT, HID / 128), 512, SMEM13>>>();
    k_gemm2<<<dim3(MAXMT, DIM / 128), 512, SMEM2>>>();
    k_combine<<<NTOK, 256>>>(out);
}

// round 15
// speedup vs baseline: 1.0987x; 1.0026x over previous
#include <cuda_runtime.h>
#include <cuda_fp16.h>
#include <cstdint>

typedef unsigned short u16;
typedef unsigned int   u32;
typedef unsigned long long u64;

#define NTOK 8192
#define DIM  1024
#define HID  2048
#define NE   8
#define MAXROWS 17408
#define MAXMT 136

__device__ int   g_counts[NE], g_fill[NE], g_ntiles;
__device__ int   g_tile_expert[MAXMT], g_tile_row0[MAXMT];
__device__ int   g_row_token[MAXROWS];
__device__ float g_row_coef[MAXROWS];
__device__ int   g_token_row[NTOK * 2];
__device__ int   g_tok_e[NTOK * 2];
__device__ float g_tok_p[NTOK * 2];

__device__ __align__(16) u16 g_Xhi[(size_t)MAXROWS * DIM];
__device__ __align__(16) u16 g_W1hi[(size_t)NE * HID * DIM];
__device__ __align__(16) u16 g_W3hi[(size_t)NE * HID * DIM];
__device__ __align__(16) u16 g_W2hi[(size_t)NE * DIM * HID];
__device__ __align__(16) u16 g_Hhi[(size_t)MAXROWS * HID];
__device__ __align__(16) float g_Orows[(size_t)MAXROWS * DIM];

__device__ __forceinline__ u16 f2h(float f) { return __half_as_ushort(__float2half_rn(f)); }
__device__ __forceinline__ u32 pk(u16 a, u16 b) { return (u32)a | ((u32)b << 16); }

__device__ __forceinline__ u32 smem_u32(const void* p) {
    u32 a;
    asm("{ .reg .u64 t; cvta.to.shared.u64 t, %1; cvt.u32.u64 %0, t; }" : "=r"(a) : "l"(p));
    return a;
}
__device__ __forceinline__ void cpa16(u32 dst, const void* src) {
    asm volatile("cp.async.cg.shared.global [%0], [%1], 16;" :: "r"(dst), "l"(src) : "memory");
}
__device__ __forceinline__ void cpa_commit() { asm volatile("cp.async.commit_group;" ::: "memory"); }
__device__ __forceinline__ void cpa_wait2() { asm volatile("cp.async.wait_group 2;" ::: "memory"); }

__device__ __forceinline__ void ldsm4(u32* r, u32 addr) {
    asm volatile("ldmatrix.sync.aligned.m8n8.x4.shared.b16 {%0,%1,%2,%3}, [%4];"
                 : "=r"(r[0]), "=r"(r[1]), "=r"(r[2]), "=r"(r[3]) : "r"(addr));
}
__device__ __forceinline__ void mma16816(float* c, const u32* a, const u32* b) {
    asm volatile(
        "mma.sync.aligned.m16n8k16.row.col.f32.f16.f16.f32 "
        "{%0,%1,%2,%3}, {%4,%5,%6,%7}, {%8,%9}, {%0,%1,%2,%3};"
        : "+f"(c[0]), "+f"(c[1]), "+f"(c[2]), "+f"(c[3])
        : "r"(a[0]), "r"(a[1]), "r"(a[2]), "r"(a[3]), "r"(b[0]), "r"(b[1]));
}

// ---------------- tiny init: counts/fill only ----------------
__global__ void k_init() {
    if (threadIdx.x < NE) { g_counts[threadIdx.x] = 0; g_fill[threadIdx.x] = 0; }
}

// ---------------- prepw: weight fp16 conversion (side stream) ----------
__global__ void k_prepw(const float* __restrict__ W1, const float* __restrict__ W2,
                        const float* __restrict__ W3) {
    int b = blockIdx.x;
    int which = b >> 14;
    size_t i = ((size_t)(b & 16383) * 256 + threadIdx.x) * 4;
    const float* src = (which == 0) ? W1 : (which == 1) ? W3 : W2;
    u16* dst = (which == 0) ? g_W1hi : (which == 1) ? g_W3hi : g_W2hi;
    float4 v = *(const float4*)(src + i);
    *(uint2*)(dst + i) = make_uint2(pk(f2h(v.x), f2h(v.y)), pk(f2h(v.z), f2h(v.w)));
}

// ---------------- gate: vectorized float4 loads ----------------
__global__ void k_gate(const float* __restrict__ x, const float* __restrict__ gw,
                       const float* __restrict__ gb) {
    int w = (blockIdx.x * blockDim.x + threadIdx.x) >> 5;
    int lane = threadIdx.x & 31;
    if (w >= NTOK) return;
    const float4* xr = (const float4*)(x + (size_t)w * DIM);
    const float4* gw4 = (const float4*)gw;
    float acc[NE];
#pragma unroll
    for (int e = 0; e < NE; e++) acc[e] = 0.f;
#pragma unroll
    for (int it = 0; it < 8; it++) {
        float4 xv = xr[lane + it * 32];
#pragma unroll
        for (int e = 0; e < NE; e++) {
            float4 wv = gw4[e * (DIM / 4) + lane + it * 32];
            acc[e] = fmaf(xv.x, wv.x, acc[e]);
            acc[e] = fmaf(xv.y, wv.y, acc[e]);
            acc[e] = fmaf(xv.z, wv.z, acc[e]);
            acc[e] = fmaf(xv.w, wv.w, acc[e]);
        }
    }
#pragma unroll
    for (int e = 0; e < NE; e++)
#pragma unroll
        for (int o = 16; o; o >>= 1) acc[e] += __shfl_xor_sync(0xffffffffu, acc[e], o);
    if (lane == 0) {
#pragma unroll
        for (int e = 0; e < NE; e++) acc[e] += gb[e];
        int e0 = 0;
#pragma unroll
        for (int e = 1; e < NE; e++) if (acc[e] > acc[e0]) e0 = e;
        int e1 = (e0 == 0) ? 1 : 0;
#pragma unroll
        for (int e = 0; e < NE; e++) if (e != e0 && acc[e] > acc[e1]) e1 = e;
        float p0 = 1.f / (1.f + expf(acc[e1] - acc[e0]));
        g_tok_e[2 * w] = e0; g_tok_e[2 * w + 1] = e1;
        g_tok_p[2 * w] = p0; g_tok_p[2 * w + 1] = 1.f - p0;
        atomicAdd(&g_counts[e0], 1);
        atomicAdd(&g_counts[e1], 1);
    }
}

// ---------------- route: offsets + assign (block-aggregated atomics) --------
__global__ void k_route() {
    __shared__ int scnt[NE], sbase[NE];
    int b = blockIdx.x, tid = threadIdx.x;

    int segs[NE], cnts[NE];
    {
        int off = 0;
#pragma unroll
        for (int e = 0; e < NE; e++) {
            segs[e] = off;
            cnts[e] = g_counts[e];
            off += ((cnts[e] + 127) >> 7) << 7;
        }
    }
    if (tid < NE) scnt[tid] = 0;
    __syncthreads();

    int t = b * 256 + tid;
    int e0 = g_tok_e[2 * t], e1 = g_tok_e[2 * t + 1];
    int l0 = atomicAdd(&scnt[e0], 1);
    int l1 = atomicAdd(&scnt[e1], 1);
    __syncthreads();
    if (tid < NE) sbase[tid] = atomicAdd(&g_fill[tid], scnt[tid]);
    __syncthreads();

    {
        int row0 = segs[e0] + sbase[e0] + l0;
        int row1 = segs[e1] + sbase[e1] + l1;
        g_row_token[row0] = t;
        g_row_coef[row0] = g_tok_p[2 * t];
        g_token_row[2 * t] = row0;
        g_row_token[row1] = t;
        g_row_coef[row1] = g_tok_p[2 * t + 1];
        g_token_row[2 * t + 1] = row1;
    }

    if (b == 0) {
        // tile map
        if (tid == 0) {
            int nt = 0;
            for (int e = 0; e < NE; e++) {
                int tt = (cnts[e] + 127) >> 7;
                for (int m = 0; m < tt; m++) {
                    g_tile_expert[nt] = e;
                    g_tile_row0[nt] = segs[e] + (m << 7);
                    nt++;
                }
            }
            g_ntiles = nt;
        }
        // padded-row token init (-1): rows between count and padded count
        int total = 0;
#pragma unroll
        for (int e = 0; e < NE; e++) {
            int pad = ((cnts[e] + 127) >> 7) << 7;
            for (int i = cnts[e] + tid; i < pad; i += 256)
                g_row_token[segs[e] + i] = -1;
            total = segs[e] + pad;
        }
        // trailing unused rows
        for (int i = total + tid; i < MAXROWS; i += 256)
            g_row_token[i] = -1;
    }
}

// ---------------- gather: full-width fp16 X copy; zeros for padded rows ----
__global__ void k_gather(const float* __restrict__ x) {
    int row = blockIdx.x;
    int t = g_row_token[row];
    size_t off = (size_t)row * DIM + threadIdx.x * 4;
    float4 v = make_float4(0.f, 0.f, 0.f, 0.f);
    if (t >= 0) v = *(const float4*)(x + (size_t)t * DIM + threadIdx.x * 4);
    *(uint2*)(g_Xhi + off) = make_uint2(pk(f2h(v.x), f2h(v.y)), pk(f2h(v.z), f2h(v.w)));
}

// ---------------- GEMM13: H = relu(X W1^T)^2 * (X W3^T) ----------------
// CTA 128x128, 512 threads (16 warps), warp tile 32x32, BK=32, 4-stage.
#define RS 80
#define S13_A  0
#define S13_B1 10240
#define S13_B3 20480
#define SS13 30720
#define SMEM13 (4 * SS13)

__device__ __forceinline__ void load13(u32 sbase, int stage, int kt,
                                       const u16* Ah, size_t wbase, int tid) {
    int k0 = kt * 32;
    u32 st = sbase + stage * SS13;
#pragma unroll
    for (int it = 0; it < 3; it++) {
        int c = tid + it * 512;
        int r = (c >> 2) & 127, ch = c & 3;
        u32 dst; const u16* src;
        if (c < 512)       { dst = st + S13_A + r * RS + ch * 16; src = Ah + (size_t)r * DIM + k0 + ch * 8; }
        else if (c < 1024) { dst = st + S13_B1 + r * RS + ch * 16; src = g_W1hi + (wbase + r) * DIM + k0 + ch * 8; }
        else               { dst = st + S13_B3 + r * RS + ch * 16; src = g_W3hi + (wbase + r) * DIM + k0 + ch * 8; }
        cpa16(dst, src);
    }
}

__global__ __launch_bounds__(512, 1)
void k_gemm13() {
    if ((int)blockIdx.x >= g_ntiles) return;
    extern __shared__ char smraw[];
    u32 sbase = smem_u32(smraw);
    int tid = threadIdx.x, wid = tid >> 5, lane = tid & 31;
    int warpM = wid >> 2, warpN = wid & 3;
    int e = g_tile_expert[blockIdx.x], row0 = g_tile_row0[blockIdx.x];
    int n0w = blockIdx.y * 128;

    const u16* Ah = g_Xhi + (size_t)row0 * DIM;
    size_t wbase = (size_t)e * HID + n0w;

    u32 aoff = (u32)((lane & 15) * RS + (lane >> 4) * 16);
    u32 b4off = (u32)(((lane & 7) + ((lane >> 4) << 3)) * RS + ((lane >> 3) & 1) * 16);
    u32 aW = (u32)(warpM * 32 * RS);
    u32 bW = (u32)(warpN * 32 * RS);

    float acc1[2][4][4], acc3[2][4][4];
#pragma unroll
    for (int mt = 0; mt < 2; mt++)
#pragma unroll
        for (int nt = 0; nt < 4; nt++)
#pragma unroll
            for (int j = 0; j < 4; j++) { acc1[mt][nt][j] = 0.f; acc3[mt][nt][j] = 0.f; }

    const int KT = DIM / 32;
    load13(sbase, 0, 0, Ah, wbase, tid); cpa_commit();
    load13(sbase, 1, 1, Ah, wbase, tid); cpa_commit();
    load13(sbase, 2, 2, Ah, wbase, tid); cpa_commit();

    for (int kt = 0; kt < KT; kt++) {
        cpa_wait2();
        __syncthreads();
        if (kt + 3 < KT) load13(sbase, (kt + 3) & 3, kt + 3, Ah, wbase, tid);
        cpa_commit();
        u32 st = sbase + (kt & 3) * SS13;
#pragma unroll
        for (int kh = 0; kh < 2; kh++) {
            u32 AH[2][4];
#pragma unroll
            for (int mt = 0; mt < 2; mt++)
                ldsm4(AH[mt], st + S13_A + aW + mt * 16 * RS + kh * 32 + aoff);
#pragma unroll
            for (int ntp = 0; ntp < 2; ntp++) {
                u32 nb = bW + ntp * 16 * RS + kh * 32 + b4off;
                u32 b1[4], b3[4];
                ldsm4(b1, st + S13_B1 + nb);
                ldsm4(b3, st + S13_B3 + nb);
#pragma unroll
                for (int sub = 0; sub < 2; sub++)
#pragma unroll
                    for (int mt = 0; mt < 2; mt++) {
                        mma16816(acc1[mt][ntp * 2 + sub], AH[mt], b1 + sub * 2);
                        mma16816(acc3[mt][ntp * 2 + sub], AH[mt], b3 + sub * 2);
                    }
            }
        }
    }

    int g4 = lane >> 2, t4 = lane & 3;
#pragma unroll
    for (int mt = 0; mt < 2; mt++) {
        int rA = row0 + warpM * 32 + mt * 16 + g4;
#pragma unroll
        for (int nt = 0; nt < 4; nt++) {
            int col = n0w + warpN * 32 + nt * 8 + t4 * 2;
            const float* d1 = acc1[mt][nt];
            const float* d3 = acc3[mt][nt];
#pragma unroll
            for (int half = 0; half < 2; half++) {
                int row = rA + half * 8;
                float r0 = fmaxf(d1[half * 2], 0.f), r1 = fmaxf(d1[half * 2 + 1], 0.f);
                float h0 = r0 * r0 * d3[half * 2];
                float h1 = r1 * r1 * d3[half * 2 + 1];
                *(u32*)(g_Hhi + (size_t)row * HID + col) = pk(f2h(h0), f2h(h1));
            }
        }
    }
}

// ---------------- GEMM2: Orows = coef * (H W2^T) ----------------
// CTA 128x128, 512 threads, warp tile 32x32, BK=32, 4-stage, 2 CTAs/SM.
#define S2_A 0
#define S2_B 10240
#define SS2 20480
#define SMEM2 (4 * SS2)

__device__ __forceinline__ void load2(u32 sbase, int stage, int kt,
                                      const u16* Ah, size_t wbase, int tid) {
    int k0 = kt * 32;
    u32 st = sbase + stage * SS2;
#pragma unroll
    for (int it = 0; it < 2; it++) {
        int c = tid + it * 512;
        int r = (c >> 2) & 127, ch = c & 3;
        u32 dst; const u16* src;
        if (c < 512) { dst = st + S2_A + r * RS + ch * 16; src = Ah + (size_t)r * HID + k0 + ch * 8; }
        else         { dst = st + S2_B + r * RS + ch * 16; src = g_W2hi + (wbase + r) * HID + k0 + ch * 8; }
        cpa16(dst, src);
    }
}

__global__ __launch_bounds__(512, 2)
void k_gemm2() {
    if ((int)blockIdx.x >= g_ntiles) return;
    extern __shared__ char smraw[];
    u32 sbase = smem_u32(smraw);
    int tid = threadIdx.x, wid = tid >> 5, lane = tid & 31;
    int warpM = wid >> 2, warpN = wid & 3;
    int e = g_tile_expert[blockIdx.x], row0 = g_tile_row0[blockIdx.x];
    int n0w = blockIdx.y * 128;

    const u16* Ah = g_Hhi + (size_t)row0 * HID;
    size_t wbase = (size_t)e * DIM + n0w;

    u32 aoff = (u32)((lane & 15) * RS + (lane >> 4) * 16);
    u32 b4off = (u32)(((lane & 7) + ((lane >> 4) << 3)) * RS + ((lane >> 3) & 1) * 16);
    u32 aW = (u32)(warpM * 32 * RS);
    u32 bW = (u32)(warpN * 32 * RS);

    float acc[2][4][4];
#pragma unroll
    for (int mt = 0; mt < 2; mt++)
#pragma unroll
        for (int nt = 0; nt < 4; nt++)
#pragma unroll
            for (int j = 0; j < 4; j++) acc[mt][nt][j] = 0.f;

    const int KT = HID / 32;
    load2(sbase, 0, 0, Ah, wbase, tid); cpa_commit();
    load2(sbase, 1, 1, Ah, wbase, tid); cpa_commit();
    load2(sbase, 2, 2, Ah, wbase, tid); cpa_commit();

    for (int kt = 0; kt < KT; kt++) {
        cpa_wait2();
        __syncthreads();
        if (kt + 3 < KT) load2(sbase, (kt + 3) & 3, kt + 3, Ah, wbase, tid);
        cpa_commit();
        u32 st = sbase + (kt & 3) * SS2;
#pragma unroll
        for (int kh = 0; kh < 2; kh++) {
            u32 AH[2][4];
#pragma unroll
            for (int mt = 0; mt < 2; mt++)
                ldsm4(AH[mt], st + S2_A + aW + mt * 16 * RS + kh * 32 + aoff);
#pragma unroll
            for (int ntp = 0; ntp < 2; ntp++) {
                u32 bh[4];
                ldsm4(bh, st + S2_B + bW + ntp * 16 * RS + kh * 32 + b4off);
#pragma unroll
                for (int sub = 0; sub < 2; sub++)
#pragma unroll
                    for (int mt = 0; mt < 2; mt++)
                        mma16816(acc[mt][ntp * 2 + sub], AH[mt], bh + sub * 2);
            }
        }
    }

    int g4 = lane >> 2, t4 = lane & 3;
#pragma unroll
    for (int mt = 0; mt < 2; mt++) {
        int rA = row0 + warpM * 32 + mt * 16 + g4;
        float c0 = g_row_coef[rA], c1 = g_row_coef[rA + 8];
#pragma unroll
        for (int nt = 0; nt < 4; nt++) {
            int col = n0w + warpN * 32 + nt * 8 + t4 * 2;
            const float* d = acc[mt][nt];
            *(float2*)(g_Orows + (size_t)rA * DIM + col) = make_float2(c0 * d[0], c0 * d[1]);
            *(float2*)(g_Orows + (size_t)(rA + 8) * DIM + col) = make_float2(c1 * d[2], c1 * d[3]);
        }
    }
}

__global__ void k_combine(float* __restrict__ out) {
    int t = blockIdx.x;
    int i = threadIdx.x * 4;
    int r0 = g_token_row[2 * t], r1 = g_token_row[2 * t + 1];
    float4 a = *(const float4*)(g_Orows + (size_t)r0 * DIM + i);
    float4 b = *(const float4*)(g_Orows + (size_t)r1 * DIM + i);
    *(float4*)(out + (size_t)t * DIM + i) =
        make_float4(a.x + b.x, a.y + b.y, a.z + b.z, a.w + b.w);
}

extern "C" void kernel_launch(void* const* d_in, const int* in_sizes, int n_in,
                              void* d_out, int out_size) {
    const float* x  = (const float*)d_in[0];
    const float* W1 = (const float*)d_in[1];
    const float* W2 = (const float*)d_in[2];
    const float* W3 = (const float*)d_in[3];
    const float* gw = (const float*)d_in[4];
    const float* gb = (const float*)d_in[5];
    float* out = (float*)d_out;

    cudaFuncSetAttribute(k_gemm13, cudaFuncAttributeMaxDynamicSharedMemorySize, SMEM13);
    cudaFuncSetAttribute(k_gemm2,  cudaFuncAttributeMaxDynamicSharedMemorySize, SMEM2);

    // fork-join: weight conversion on a side stream, routing chain on main.
    cudaStream_t s1;
    cudaEvent_t evFork, evJoin;
    cudaStreamCreateWithFlags(&s1, cudaStreamNonBlocking);
    cudaEventCreateWithFlags(&evFork, cudaEventDisableTiming);
    cudaEventCreateWithFlags(&evJoin, cudaEventDisableTiming);

    cudaEventRecord(evFork, 0);
    cudaStreamWaitEvent(s1, evFork, 0);
    k_prepw<<<49152, 256, 0, s1>>>(W1, W2, W3);
    cudaEventRecord(evJoin, s1);

    k_init<<<1, 256>>>();
    k_gate<<<1024, 256>>>(x, gw, gb);
    k_route<<<32, 256>>>();
    k_gather<<<MAXROWS, 256>>>(x);

    cudaStreamWaitEvent(0, evJoin, 0);
    k_gemm13<<<dim3(MAXMT, HID / 128), 512, SMEM13>>>();
    k_gemm2<<<dim3(MAXMT, DIM / 128), 512, SMEM2>>>();
    k_combine<<<NTOK, 256>>>(out);
}

// round 16
// speedup vs baseline: 1.1511x; 1.0477x over previous
#include <cuda_runtime.h>
#include <cuda_fp16.h>
#include <cstdint>

typedef unsigned short u16;
typedef unsigned int   u32;
typedef unsigned long long u64;

#define NTOK 8192
#define DIM  1024
#define HID  2048
#define NE   8
#define MAXROWS 17408
#define MAXMT 136

__device__ int   g_counts[NE], g_fill[NE], g_ntiles;
__device__ int   g_tile_expert[MAXMT], g_tile_row0[MAXMT];
__device__ int   g_row_token[MAXROWS];
__device__ float g_row_coef[MAXROWS];
__device__ int   g_token_row[NTOK * 2];
__device__ int   g_tok_e[NTOK * 2];
__device__ float g_tok_p[NTOK * 2];

__device__ __align__(16) u16 g_Xhi[(size_t)MAXROWS * DIM];
__device__ __align__(16) u16 g_W1hi[(size_t)NE * HID * DIM];
__device__ __align__(16) u16 g_W3hi[(size_t)NE * HID * DIM];
__device__ __align__(16) u16 g_W2hi[(size_t)NE * DIM * HID];
__device__ __align__(16) u16 g_Hhi[(size_t)MAXROWS * HID];
__device__ __align__(16) float g_Orows[(size_t)MAXROWS * DIM];

__device__ __forceinline__ u16 f2h(float f) { return __half_as_ushort(__float2half_rn(f)); }
__device__ __forceinline__ u32 pk(u16 a, u16 b) { return (u32)a | ((u32)b << 16); }

__device__ __forceinline__ u32 smem_u32(const void* p) {
    u32 a;
    asm("{ .reg .u64 t; cvta.to.shared.u64 t, %1; cvt.u32.u64 %0, t; }" : "=r"(a) : "l"(p));
    return a;
}
__device__ __forceinline__ void cpa16(u32 dst, const void* src) {
    asm volatile("cp.async.cg.shared.global [%0], [%1], 16;" :: "r"(dst), "l"(src) : "memory");
}
__device__ __forceinline__ void cpa_commit() { asm volatile("cp.async.commit_group;" ::: "memory"); }
__device__ __forceinline__ void cpa_wait1() { asm volatile("cp.async.wait_group 1;" ::: "memory"); }

__device__ __forceinline__ void ldsm4(u32* r, u32 addr) {
    asm volatile("ldmatrix.sync.aligned.m8n8.x4.shared.b16 {%0,%1,%2,%3}, [%4];"
                 : "=r"(r[0]), "=r"(r[1]), "=r"(r[2]), "=r"(r[3]) : "r"(addr));
}
__device__ __forceinline__ void mma16816(float* c, const u32* a, const u32* b) {
    asm volatile(
        "mma.sync.aligned.m16n8k16.row.col.f32.f16.f16.f32 "
        "{%0,%1,%2,%3}, {%4,%5,%6,%7}, {%8,%9}, {%0,%1,%2,%3};"
        : "+f"(c[0]), "+f"(c[1]), "+f"(c[2]), "+f"(c[3])
        : "r"(a[0]), "r"(a[1]), "r"(a[2]), "r"(a[3]), "r"(b[0]), "r"(b[1]));
}

// ---------------- tiny init: counts/fill only ----------------
__global__ void k_init() {
    if (threadIdx.x < NE) { g_counts[threadIdx.x] = 0; g_fill[threadIdx.x] = 0; }
}

// ---------------- prepw: weight fp16 conversion (side stream) ----------
__global__ void k_prepw(const float* __restrict__ W1, const float* __restrict__ W2,
                        const float* __restrict__ W3) {
    int b = blockIdx.x;
    int which = b >> 14;
    size_t i = ((size_t)(b & 16383) * 256 + threadIdx.x) * 4;
    const float* src = (which == 0) ? W1 : (which == 1) ? W3 : W2;
    u16* dst = (which == 0) ? g_W1hi : (which == 1) ? g_W3hi : g_W2hi;
    float4 v = *(const float4*)(src + i);
    *(uint2*)(dst + i) = make_uint2(pk(f2h(v.x), f2h(v.y)), pk(f2h(v.z), f2h(v.w)));
}

// ---------------- gate: vectorized float4 loads ----------------
__global__ void k_gate(const float* __restrict__ x, const float* __restrict__ gw,
                       const float* __restrict__ gb) {
    int w = (blockIdx.x * blockDim.x + threadIdx.x) >> 5;
    int lane = threadIdx.x & 31;
    if (w >= NTOK) return;
    const float4* xr = (const float4*)(x + (size_t)w * DIM);
    const float4* gw4 = (const float4*)gw;
    float acc[NE];
#pragma unroll
    for (int e = 0; e < NE; e++) acc[e] = 0.f;
#pragma unroll
    for (int it = 0; it < 8; it++) {
        float4 xv = xr[lane + it * 32];
#pragma unroll
        for (int e = 0; e < NE; e++) {
            float4 wv = gw4[e * (DIM / 4) + lane + it * 32];
            acc[e] = fmaf(xv.x, wv.x, acc[e]);
            acc[e] = fmaf(xv.y, wv.y, acc[e]);
            acc[e] = fmaf(xv.z, wv.z, acc[e]);
            acc[e] = fmaf(xv.w, wv.w, acc[e]);
        }
    }
#pragma unroll
    for (int e = 0; e < NE; e++)
#pragma unroll
        for (int o = 16; o; o >>= 1) acc[e] += __shfl_xor_sync(0xffffffffu, acc[e], o);
    if (lane == 0) {
#pragma unroll
        for (int e = 0; e < NE; e++) acc[e] += gb[e];
        int e0 = 0;
#pragma unroll
        for (int e = 1; e < NE; e++) if (acc[e] > acc[e0]) e0 = e;
        int e1 = (e0 == 0) ? 1 : 0;
#pragma unroll
        for (int e = 0; e < NE; e++) if (e != e0 && acc[e] > acc[e1]) e1 = e;
        float p0 = 1.f / (1.f + expf(acc[e1] - acc[e0]));
        g_tok_e[2 * w] = e0; g_tok_e[2 * w + 1] = e1;
        g_tok_p[2 * w] = p0; g_tok_p[2 * w + 1] = 1.f - p0;
        atomicAdd(&g_counts[e0], 1);
        atomicAdd(&g_counts[e1], 1);
    }
}

// ---------------- route: offsets + assign (block-aggregated atomics) --------
__global__ void k_route() {
    __shared__ int scnt[NE], sbase[NE];
    int b = blockIdx.x, tid = threadIdx.x;

    int segs[NE], cnts[NE];
    {
        int off = 0;
#pragma unroll
        for (int e = 0; e < NE; e++) {
            segs[e] = off;
            cnts[e] = g_counts[e];
            off += ((cnts[e] + 127) >> 7) << 7;
        }
    }
    if (tid < NE) scnt[tid] = 0;
    __syncthreads();

    int t = b * 256 + tid;
    int e0 = g_tok_e[2 * t], e1 = g_tok_e[2 * t + 1];
    int l0 = atomicAdd(&scnt[e0], 1);
    int l1 = atomicAdd(&scnt[e1], 1);
    __syncthreads();
    if (tid < NE) sbase[tid] = atomicAdd(&g_fill[tid], scnt[tid]);
    __syncthreads();

    {
        int row0 = segs[e0] + sbase[e0] + l0;
        int row1 = segs[e1] + sbase[e1] + l1;
        g_row_token[row0] = t;
        g_row_coef[row0] = g_tok_p[2 * t];
        g_token_row[2 * t] = row0;
        g_row_token[row1] = t;
        g_row_coef[row1] = g_tok_p[2 * t + 1];
        g_token_row[2 * t + 1] = row1;
    }

    if (b == 0) {
        if (tid == 0) {
            int nt = 0;
            for (int e = 0; e < NE; e++) {
                int tt = (cnts[e] + 127) >> 7;
                for (int m = 0; m < tt; m++) {
                    g_tile_expert[nt] = e;
                    g_tile_row0[nt] = segs[e] + (m << 7);
                    nt++;
                }
            }
            g_ntiles = nt;
        }
        int total = 0;
#pragma unroll
        for (int e = 0; e < NE; e++) {
            int pad = ((cnts[e] + 127) >> 7) << 7;
            for (int i = cnts[e] + tid; i < pad; i += 256)
                g_row_token[segs[e] + i] = -1;
            total = segs[e] + pad;
        }
        for (int i = total + tid; i < MAXROWS; i += 256)
            g_row_token[i] = -1;
    }
}

// ---------------- gather: full-width fp16 X copy; zeros for padded rows ----
__global__ void k_gather(const float* __restrict__ x) {
    int row = blockIdx.x;
    int t = g_row_token[row];
    size_t off = (size_t)row * DIM + threadIdx.x * 4;
    float4 v = make_float4(0.f, 0.f, 0.f, 0.f);
    if (t >= 0) v = *(const float4*)(x + (size_t)t * DIM + threadIdx.x * 4);
    *(uint2*)(g_Xhi + off) = make_uint2(pk(f2h(v.x), f2h(v.y)), pk(f2h(v.z), f2h(v.w)));
}

// ---------------- GEMM13: H = relu(X W1^T)^2 * (X W3^T) ----------------
// CTA 128x128, 512 threads (16 warps), warp tile 32x32, BK=64, 3-stage,
// single barrier per K-tile, load-distance 2. Rows padded to 144B.
#define RS 144
#define S13_A  0
#define S13_B1 18432
#define S13_B3 36864
#define SS13 55296
#define SMEM13 (3 * SS13)

__device__ __forceinline__ void load13(u32 sbase, int stage, int kt,
                                       const u16* Ah, size_t wbase, int tid) {
    int k0 = kt * 64;
    u32 st = sbase + stage * SS13;
#pragma unroll
    for (int it = 0; it < 6; it++) {
        int c = tid + it * 512;
        int r = (c >> 3) & 127, ch = c & 7;
        u32 dst; const u16* src;
        if (c < 1024)      { dst = st + S13_A + r * RS + ch * 16; src = Ah + (size_t)r * DIM + k0 + ch * 8; }
        else if (c < 2048) { dst = st + S13_B1 + r * RS + ch * 16; src = g_W1hi + (wbase + r) * DIM + k0 + ch * 8; }
        else               { dst = st + S13_B3 + r * RS + ch * 16; src = g_W3hi + (wbase + r) * DIM + k0 + ch * 8; }
        cpa16(dst, src);
    }
}

__global__ __launch_bounds__(512, 1)
void k_gemm13() {
    if ((int)blockIdx.x >= g_ntiles) return;
    extern __shared__ char smraw[];
    u32 sbase = smem_u32(smraw);
    int tid = threadIdx.x, wid = tid >> 5, lane = tid & 31;
    int warpM = wid >> 2, warpN = wid & 3;
    int e = g_tile_expert[blockIdx.x], row0 = g_tile_row0[blockIdx.x];
    int n0w = blockIdx.y * 128;

    const u16* Ah = g_Xhi + (size_t)row0 * DIM;
    size_t wbase = (size_t)e * HID + n0w;

    u32 aoff = (u32)((lane & 15) * RS + (lane >> 4) * 16);
    u32 b4off = (u32)(((lane & 7) + ((lane >> 4) << 3)) * RS + ((lane >> 3) & 1) * 16);
    u32 aW = (u32)(warpM * 32 * RS);
    u32 bW = (u32)(warpN * 32 * RS);

    float acc1[2][4][4], acc3[2][4][4];
#pragma unroll
    for (int mt = 0; mt < 2; mt++)
#pragma unroll
        for (int nt = 0; nt < 4; nt++)
#pragma unroll
            for (int j = 0; j < 4; j++) { acc1[mt][nt][j] = 0.f; acc3[mt][nt][j] = 0.f; }

    const int KT = DIM / 64;  // 16
    load13(sbase, 0, 0, Ah, wbase, tid); cpa_commit();
    load13(sbase, 1, 1, Ah, wbase, tid); cpa_commit();

    int stage = 0, nstage = 2;
    for (int kt = 0; kt < KT; kt++) {
        cpa_wait1();
        __syncthreads();
        if (kt + 2 < KT) load13(sbase, nstage, kt + 2, Ah, wbase, tid);
        cpa_commit();
        u32 st = sbase + stage * SS13;
#pragma unroll
        for (int kh = 0; kh < 4; kh++) {
            u32 AH[2][4];
#pragma unroll
            for (int mt = 0; mt < 2; mt++)
                ldsm4(AH[mt], st + S13_A + aW + mt * 16 * RS + kh * 32 + aoff);
#pragma unroll
            for (int ntp = 0; ntp < 2; ntp++) {
                u32 nb = bW + ntp * 16 * RS + kh * 32 + b4off;
                u32 b1[4], b3[4];
                ldsm4(b1, st + S13_B1 + nb);
                ldsm4(b3, st + S13_B3 + nb);
#pragma unroll
                for (int sub = 0; sub < 2; sub++)
#pragma unroll
                    for (int mt = 0; mt < 2; mt++) {
                        mma16816(acc1[mt][ntp * 2 + sub], AH[mt], b1 + sub * 2);
                        mma16816(acc3[mt][ntp * 2 + sub], AH[mt], b3 + sub * 2);
                    }
            }
        }
        stage = (stage == 2) ? 0 : stage + 1;
        nstage = (nstage == 2) ? 0 : nstage + 1;
    }

    int g4 = lane >> 2, t4 = lane & 3;
#pragma unroll
    for (int mt = 0; mt < 2; mt++) {
        int rA = row0 + warpM * 32 + mt * 16 + g4;
#pragma unroll
        for (int nt = 0; nt < 4; nt++) {
            int col = n0w + warpN * 32 + nt * 8 + t4 * 2;
            const float* d1 = acc1[mt][nt];
            const float* d3 = acc3[mt][nt];
#pragma unroll
            for (int half = 0; half < 2; half++) {
                int row = rA + half * 8;
                float r0 = fmaxf(d1[half * 2], 0.f), r1 = fmaxf(d1[half * 2 + 1], 0.f);
                float h0 = r0 * r0 * d3[half * 2];
                float h1 = r1 * r1 * d3[half * 2 + 1];
                *(u32*)(g_Hhi + (size_t)row * HID + col) = pk(f2h(h0), f2h(h1));
            }
        }
    }
}

// ---------------- GEMM2: Orows = coef * (H W2^T) ----------------
// CTA 128x128, 512 threads, warp tile 32x32, BK=64, 3-stage, 2 CTAs/SM.
#define S2_A 0
#define S2_B 18432
#define SS2 36864
#define SMEM2 (3 * SS2)

__device__ __forceinline__ void load2(u32 sbase, int stage, int kt,
                                      const u16* Ah, size_t wbase, int tid) {
    int k0 = kt * 64;
    u32 st = sbase + stage * SS2;
#pragma unroll
    for (int it = 0; it < 4; it++) {
        int c = tid + it * 512;
        int r = (c >> 3) & 127, ch = c & 7;
        u32 dst; const u16* src;
        if (c < 1024) { dst = st + S2_A + r * RS + ch * 16; src = Ah + (size_t)r * HID + k0 + ch * 8; }
        else          { dst = st + S2_B + r * RS + ch * 16; src = g_W2hi + (wbase + r) * HID + k0 + ch * 8; }
        cpa16(dst, src);
    }
}

__global__ __launch_bounds__(512, 2)
void k_gemm2() {
    if ((int)blockIdx.x >= g_ntiles) return;
    extern __shared__ char smraw[];
    u32 sbase = smem_u32(smraw);
    int tid = threadIdx.x, wid = tid >> 5, lane = tid & 31;
    int warpM = wid >> 2, warpN = wid & 3;
    int e = g_tile_expert[blockIdx.x], row0 = g_tile_row0[blockIdx.x];
    int n0w = blockIdx.y * 128;

    const u16* Ah = g_Hhi + (size_t)row0 * HID;
    size_t wbase = (size_t)e * DIM + n0w;

    u32 aoff = (u32)((lane & 15) * RS + (lane >> 4) * 16);
    u32 b4off = (u32)(((lane & 7) + ((lane >> 4) << 3)) * RS + ((lane >> 3) & 1) * 16);
    u32 aW = (u32)(warpM * 32 * RS);
    u32 bW = (u32)(warpN * 32 * RS);

    float acc[2][4][4];
#pragma unroll
    for (int mt = 0; mt < 2; mt++)
#pragma unroll
        for (int nt = 0; nt < 4; nt++)
#pragma unroll
            for (int j = 0; j < 4; j++) acc[mt][nt][j] = 0.f;

    const int KT = HID / 64;  // 32
    load2(sbase, 0, 0, Ah, wbase, tid); cpa_commit();
    load2(sbase, 1, 1, Ah, wbase, tid); cpa_commit();

    int stage = 0, nstage = 2;
    for (int kt = 0; kt < KT; kt++) {
        cpa_wait1();
        __syncthreads();
        if (kt + 2 < KT) load2(sbase, nstage, kt + 2, Ah, wbase, tid);
        cpa_commit();
        u32 st = sbase + stage * SS2;
#pragma unroll
        for (int kh = 0; kh < 4; kh++) {
            u32 AH[2][4];
#pragma unroll
            for (int mt = 0; mt < 2; mt++)
                ldsm4(AH[mt], st + S2_A + aW + mt * 16 * RS + kh * 32 + aoff);
#pragma unroll
            for (int ntp = 0; ntp < 2; ntp++) {
                u32 bh[4];
                ldsm4(bh, st + S2_B + bW + ntp * 16 * RS + kh * 32 + b4off);
#pragma unroll
                for (int sub = 0; sub < 2; sub++)
#pragma unroll
                    for (int mt = 0; mt < 2; mt++)
                        mma16816(acc[mt][ntp * 2 + sub], AH[mt], bh + sub * 2);
            }
        }
        stage = (stage == 2) ? 0 : stage + 1;
        nstage = (nstage == 2) ? 0 : nstage + 1;
    }

    int g4 = lane >> 2, t4 = lane & 3;
#pragma unroll
    for (int mt = 0; mt < 2; mt++) {
        int rA = row0 + warpM * 32 + mt * 16 + g4;
        float c0 = g_row_coef[rA], c1 = g_row_coef[rA + 8];
#pragma unroll
        for (int nt = 0; nt < 4; nt++) {
            int col = n0w + warpN * 32 + nt * 8 + t4 * 2;
            const float* d = acc[mt][nt];
            *(float2*)(g_Orows + (size_t)rA * DIM + col) = make_float2(c0 * d[0], c0 * d[1]);
            *(float2*)(g_Orows + (size_t)(rA + 8) * DIM + col) = make_float2(c1 * d[2], c1 * d[3]);
        }
    }
}

__global__ void k_combine(float* __restrict__ out) {
    int t = blockIdx.x;
    int i = threadIdx.x * 4;
    int r0 = g_token_row[2 * t], r1 = g_token_row[2 * t + 1];
    float4 a = *(const float4*)(g_Orows + (size_t)r0 * DIM + i);
    float4 b = *(const float4*)(g_Orows + (size_t)r1 * DIM + i);
    *(float4*)(out + (size_t)t * DIM + i) =
        make_float4(a.x + b.x, a.y + b.y, a.z + b.z, a.w + b.w);
}

extern "C" void kernel_launch(void* const* d_in, const int* in_sizes, int n_in,
                              void* d_out, int out_size) {
    const float* x  = (const float*)d_in[0];
    const float* W1 = (const float*)d_in[1];
    const float* W2 = (const float*)d_in[2];
    const float* W3 = (const float*)d_in[3];
    const float* gw = (const float*)d_in[4];
    const float* gb = (const float*)d_in[5];
    float* out = (float*)d_out;

    cudaFuncSetAttribute(k_gemm13, cudaFuncAttributeMaxDynamicSharedMemorySize, SMEM13);
    cudaFuncSetAttribute(k_gemm2,  cudaFuncAttributeMaxDynamicSharedMemorySize, SMEM2);

    // fork-join: weight conversion on a side stream, routing chain on main.
    cudaStream_t s1;
    cudaEvent_t evFork, evJoin;
    cudaStreamCreateWithFlags(&s1, cudaStreamNonBlocking);
    cudaEventCreateWithFlags(&evFork, cudaEventDisableTiming);
    cudaEventCreateWithFlags(&evJoin, cudaEventDisableTiming);

    cudaEventRecord(evFork, 0);
    cudaStreamWaitEvent(s1, evFork, 0);
    k_prepw<<<49152, 256, 0, s1>>>(W1, W2, W3);
    cudaEventRecord(evJoin, s1);

    k_init<<<1, 256>>>();
    k_gate<<<1024, 256>>>(x, gw, gb);
    k_route<<<32, 256>>>();
    k_gather<<<MAXROWS, 256>>>(x);

    cudaStreamWaitEvent(0, evJoin, 0);
    k_gemm13<<<dim3(MAXMT, HID / 128), 512, SMEM13>>>();
    k_gemm2<<<dim3(MAXMT, DIM / 128), 512, SMEM2>>>();
    k_combine<<<NTOK, 256>>>(out);
}

// round 17
// speedup vs baseline: 1.1547x; 1.0031x over previous
#include <cuda_runtime.h>
#include <cuda_fp16.h>
#include <cstdint>

typedef unsigned short u16;
typedef unsigned int   u32;
typedef unsigned long long u64;

#define NTOK 8192
#define DIM  1024
#define HID  2048
#define NE   8
#define MAXROWS 17408
#define MAXMT 136

__device__ int   g_counts[NE], g_fill[NE], g_ntiles;
__device__ int   g_tile_expert[MAXMT], g_tile_row0[MAXMT];
__device__ int   g_row_token[MAXROWS];
__device__ float g_row_coef[MAXROWS];
__device__ int   g_token_row[NTOK * 2];
__device__ int   g_tok_e[NTOK * 2];
__device__ float g_tok_p[NTOK * 2];

__device__ __align__(16) u16 g_Xhi[(size_t)MAXROWS * DIM];
__device__ __align__(16) u16 g_W1hi[(size_t)NE * HID * DIM];
__device__ __align__(16) u16 g_W3hi[(size_t)NE * HID * DIM];
__device__ __align__(16) u16 g_W2hi[(size_t)NE * DIM * HID];
__device__ __align__(16) u16 g_Hhi[(size_t)MAXROWS * HID];
__device__ __align__(16) float g_Orows[(size_t)MAXROWS * DIM];

__device__ __forceinline__ u16 f2h(float f) { return __half_as_ushort(__float2half_rn(f)); }
__device__ __forceinline__ u32 pk(u16 a, u16 b) { return (u32)a | ((u32)b << 16); }

__device__ __forceinline__ u32 smem_u32(const void* p) {
    u32 a;
    asm("{ .reg .u64 t; cvta.to.shared.u64 t, %1; cvt.u32.u64 %0, t; }" : "=r"(a) : "l"(p));
    return a;
}
__device__ __forceinline__ void cpa16(u32 dst, const void* src) {
    asm volatile("cp.async.cg.shared.global [%0], [%1], 16;" :: "r"(dst), "l"(src) : "memory");
}
__device__ __forceinline__ void cpa_commit() { asm volatile("cp.async.commit_group;" ::: "memory"); }
__device__ __forceinline__ void cpa_wait1() { asm volatile("cp.async.wait_group 1;" ::: "memory"); }

__device__ __forceinline__ void ldsm4(u32* r, u32 addr) {
    asm volatile("ldmatrix.sync.aligned.m8n8.x4.shared.b16 {%0,%1,%2,%3}, [%4];"
                 : "=r"(r[0]), "=r"(r[1]), "=r"(r[2]), "=r"(r[3]) : "r"(addr));
}
__device__ __forceinline__ void mma16816(float* c, const u32* a, const u32* b) {
    asm volatile(
        "mma.sync.aligned.m16n8k16.row.col.f32.f16.f16.f32 "
        "{%0,%1,%2,%3}, {%4,%5,%6,%7}, {%8,%9}, {%0,%1,%2,%3};"
        : "+f"(c[0]), "+f"(c[1]), "+f"(c[2]), "+f"(c[3])
        : "r"(a[0]), "r"(a[1]), "r"(a[2]), "r"(a[3]), "r"(b[0]), "r"(b[1]));
}

// ---------------- tiny init: counts/fill only ----------------
__global__ void k_init() {
    if (threadIdx.x < NE) { g_counts[threadIdx.x] = 0; g_fill[threadIdx.x] = 0; }
}

// ---------------- prepw13: W1+W3 fp16 conversion (side stream, joins gemm13) --
__global__ void k_prepw13(const float* __restrict__ W1, const float* __restrict__ W3) {
    int b = blockIdx.x;
    int which = b >> 14;
    size_t i = ((size_t)(b & 16383) * 256 + threadIdx.x) * 4;
    const float* src = (which == 0) ? W1 : W3;
    u16* dst = (which == 0) ? g_W1hi : g_W3hi;
    float4 v = *(const float4*)(src + i);
    *(uint2*)(dst + i) = make_uint2(pk(f2h(v.x), f2h(v.y)), pk(f2h(v.z), f2h(v.w)));
}

// ---------------- prepw2: W2 fp16 conversion (overlaps gemm13) --------------
__global__ void k_prepw2(const float* __restrict__ W2) {
    size_t i = ((size_t)blockIdx.x * 256 + threadIdx.x) * 4;
    float4 v = *(const float4*)(W2 + i);
    *(uint2*)(g_W2hi + i) = make_uint2(pk(f2h(v.x), f2h(v.y)), pk(f2h(v.z), f2h(v.w)));
}

// ---------------- gate: vectorized float4 loads ----------------
__global__ void k_gate(const float* __restrict__ x, const float* __restrict__ gw,
                       const float* __restrict__ gb) {
    int w = (blockIdx.x * blockDim.x + threadIdx.x) >> 5;
    int lane = threadIdx.x & 31;
    if (w >= NTOK) return;
    const float4* xr = (const float4*)(x + (size_t)w * DIM);
    const float4* gw4 = (const float4*)gw;
    float acc[NE];
#pragma unroll
    for (int e = 0; e < NE; e++) acc[e] = 0.f;
#pragma unroll
    for (int it = 0; it < 8; it++) {
        float4 xv = xr[lane + it * 32];
#pragma unroll
        for (int e = 0; e < NE; e++) {
            float4 wv = gw4[e * (DIM / 4) + lane + it * 32];
            acc[e] = fmaf(xv.x, wv.x, acc[e]);
            acc[e] = fmaf(xv.y, wv.y, acc[e]);
            acc[e] = fmaf(xv.z, wv.z, acc[e]);
            acc[e] = fmaf(xv.w, wv.w, acc[e]);
        }
    }
#pragma unroll
    for (int e = 0; e < NE; e++)
#pragma unroll
        for (int o = 16; o; o >>= 1) acc[e] += __shfl_xor_sync(0xffffffffu, acc[e], o);
    if (lane == 0) {
#pragma unroll
        for (int e = 0; e < NE; e++) acc[e] += gb[e];
        int e0 = 0;
#pragma unroll
        for (int e = 1; e < NE; e++) if (acc[e] > acc[e0]) e0 = e;
        int e1 = (e0 == 0) ? 1 : 0;
#pragma unroll
        for (int e = 0; e < NE; e++) if (e != e0 && acc[e] > acc[e1]) e1 = e;
        float p0 = 1.f / (1.f + expf(acc[e1] - acc[e0]));
        g_tok_e[2 * w] = e0; g_tok_e[2 * w + 1] = e1;
        g_tok_p[2 * w] = p0; g_tok_p[2 * w + 1] = 1.f - p0;
        atomicAdd(&g_counts[e0], 1);
        atomicAdd(&g_counts[e1], 1);
    }
}

// ---------------- route: offsets + assign (block-aggregated atomics) --------
__global__ void k_route() {
    __shared__ int scnt[NE], sbase[NE];
    int b = blockIdx.x, tid = threadIdx.x;

    int segs[NE], cnts[NE];
    {
        int off = 0;
#pragma unroll
        for (int e = 0; e < NE; e++) {
            segs[e] = off;
            cnts[e] = g_counts[e];
            off += ((cnts[e] + 127) >> 7) << 7;
        }
    }
    if (tid < NE) scnt[tid] = 0;
    __syncthreads();

    int t = b * 256 + tid;
    int e0 = g_tok_e[2 * t], e1 = g_tok_e[2 * t + 1];
    int l0 = atomicAdd(&scnt[e0], 1);
    int l1 = atomicAdd(&scnt[e1], 1);
    __syncthreads();
    if (tid < NE) sbase[tid] = atomicAdd(&g_fill[tid], scnt[tid]);
    __syncthreads();

    {
        int row0 = segs[e0] + sbase[e0] + l0;
        int row1 = segs[e1] + sbase[e1] + l1;
        g_row_token[row0] = t;
        g_row_coef[row0] = g_tok_p[2 * t];
        g_token_row[2 * t] = row0;
        g_row_token[row1] = t;
        g_row_coef[row1] = g_tok_p[2 * t + 1];
        g_token_row[2 * t + 1] = row1;
    }

    if (b == 0) {
        if (tid == 0) {
            int nt = 0;
            for (int e = 0; e < NE; e++) {
                int tt = (cnts[e] + 127) >> 7;
                for (int m = 0; m < tt; m++) {
                    g_tile_expert[nt] = e;
                    g_tile_row0[nt] = segs[e] + (m << 7);
                    nt++;
                }
            }
            g_ntiles = nt;
        }
        int total = 0;
#pragma unroll
        for (int e = 0; e < NE; e++) {
            int pad = ((cnts[e] + 127) >> 7) << 7;
            for (int i = cnts[e] + tid; i < pad; i += 256)
                g_row_token[segs[e] + i] = -1;
            total = segs[e] + pad;
        }
        for (int i = total + tid; i < MAXROWS; i += 256)
            g_row_token[i] = -1;
    }
}

// ---------------- gather: full-width fp16 X copy; zeros for padded rows ----
__global__ void k_gather(const float* __restrict__ x) {
    int row = blockIdx.x;
    int t = g_row_token[row];
    size_t off = (size_t)row * DIM + threadIdx.x * 4;
    float4 v = make_float4(0.f, 0.f, 0.f, 0.f);
    if (t >= 0) v = *(const float4*)(x + (size_t)t * DIM + threadIdx.x * 4);
    *(uint2*)(g_Xhi + off) = make_uint2(pk(f2h(v.x), f2h(v.y)), pk(f2h(v.z), f2h(v.w)));
}

// ---------------- GEMM13: H = relu(X W1^T)^2 * (X W3^T) ----------------
// CTA 128x128, 512 threads (16 warps), warp tile 32x32, BK=64, 3-stage,
// single barrier per K-tile, load-distance 2. Rows padded to 144B.
#define RS 144
#define S13_A  0
#define S13_B1 18432
#define S13_B3 36864
#define SS13 55296
#define SMEM13 (3 * SS13)

__device__ __forceinline__ void load13(u32 sbase, int stage, int kt,
                                       const u16* Ah, size_t wbase, int tid) {
    int k0 = kt * 64;
    u32 st = sbase + stage * SS13;
#pragma unroll
    for (int it = 0; it < 6; it++) {
        int c = tid + it * 512;
        int r = (c >> 3) & 127, ch = c & 7;
        u32 dst; const u16* src;
        if (c < 1024)      { dst = st + S13_A + r * RS + ch * 16; src = Ah + (size_t)r * DIM + k0 + ch * 8; }
        else if (c < 2048) { dst = st + S13_B1 + r * RS + ch * 16; src = g_W1hi + (wbase + r) * DIM + k0 + ch * 8; }
        else               { dst = st + S13_B3 + r * RS + ch * 16; src = g_W3hi + (wbase + r) * DIM + k0 + ch * 8; }
        cpa16(dst, src);
    }
}

__global__ __launch_bounds__(512, 1)
void k_gemm13() {
    if ((int)blockIdx.x >= g_ntiles) return;
    extern __shared__ char smraw[];
    u32 sbase = smem_u32(smraw);
    int tid = threadIdx.x, wid = tid >> 5, lane = tid & 31;
    int warpM = wid >> 2, warpN = wid & 3;
    int e = g_tile_expert[blockIdx.x], row0 = g_tile_row0[blockIdx.x];
    int n0w = blockIdx.y * 128;

    const u16* Ah = g_Xhi + (size_t)row0 * DIM;
    size_t wbase = (size_t)e * HID + n0w;

    u32 aoff = (u32)((lane & 15) * RS + (lane >> 4) * 16);
    u32 b4off = (u32)(((lane & 7) + ((lane >> 4) << 3)) * RS + ((lane >> 3) & 1) * 16);
    u32 aW = (u32)(warpM * 32 * RS);
    u32 bW = (u32)(warpN * 32 * RS);

    float acc1[2][4][4], acc3[2][4][4];
#pragma unroll
    for (int mt = 0; mt < 2; mt++)
#pragma unroll
        for (int nt = 0; nt < 4; nt++)
#pragma unroll
            for (int j = 0; j < 4; j++) { acc1[mt][nt][j] = 0.f; acc3[mt][nt][j] = 0.f; }

    const int KT = DIM / 64;  // 16
    load13(sbase, 0, 0, Ah, wbase, tid); cpa_commit();
    load13(sbase, 1, 1, Ah, wbase, tid); cpa_commit();

    int stage = 0, nstage = 2;
    for (int kt = 0; kt < KT; kt++) {
        cpa_wait1();
        __syncthreads();
        if (kt + 2 < KT) load13(sbase, nstage, kt + 2, Ah, wbase, tid);
        cpa_commit();
        u32 st = sbase + stage * SS13;
#pragma unroll
        for (int kh = 0; kh < 4; kh++) {
            u32 AH[2][4];
#pragma unroll
            for (int mt = 0; mt < 2; mt++)
                ldsm4(AH[mt], st + S13_A + aW + mt * 16 * RS + kh * 32 + aoff);
#pragma unroll
            for (int ntp = 0; ntp < 2; ntp++) {
                u32 nb = bW + ntp * 16 * RS + kh * 32 + b4off;
                u32 b1[4], b3[4];
                ldsm4(b1, st + S13_B1 + nb);
                ldsm4(b3, st + S13_B3 + nb);
#pragma unroll
                for (int sub = 0; sub < 2; sub++)
#pragma unroll
                    for (int mt = 0; mt < 2; mt++) {
                        mma16816(acc1[mt][ntp * 2 + sub], AH[mt], b1 + sub * 2);
                        mma16816(acc3[mt][ntp * 2 + sub], AH[mt], b3 + sub * 2);
                    }
            }
        }
        stage = (stage == 2) ? 0 : stage + 1;
        nstage = (nstage == 2) ? 0 : nstage + 1;
    }

    int g4 = lane >> 2, t4 = lane & 3;
#pragma unroll
    for (int mt = 0; mt < 2; mt++) {
        int rA = row0 + warpM * 32 + mt * 16 + g4;
#pragma unroll
        for (int nt = 0; nt < 4; nt++) {
            int col = n0w + warpN * 32 + nt * 8 + t4 * 2;
            const float* d1 = acc1[mt][nt];
            const float* d3 = acc3[mt][nt];
#pragma unroll
            for (int half = 0; half < 2; half++) {
                int row = rA + half * 8;
                float r0 = fmaxf(d1[half * 2], 0.f), r1 = fmaxf(d1[half * 2 + 1], 0.f);
                float h0 = r0 * r0 * d3[half * 2];
                float h1 = r1 * r1 * d3[half * 2 + 1];
                *(u32*)(g_Hhi + (size_t)row * HID + col) = pk(f2h(h0), f2h(h1));
            }
        }
    }
}

// ---------------- GEMM2: Orows = coef * (H W2^T) ----------------
// CTA 128x128, 512 threads, warp tile 32x32, BK=64, 3-stage, 2 CTAs/SM.
#define S2_A 0
#define S2_B 18432
#define SS2 36864
#define SMEM2 (3 * SS2)

__device__ __forceinline__ void load2(u32 sbase, int stage, int kt,
                                      const u16* Ah, size_t wbase, int tid) {
    int k0 = kt * 64;
    u32 st = sbase + stage * SS2;
#pragma unroll
    for (int it = 0; it < 4; it++) {
        int c = tid + it * 512;
        int r = (c >> 3) & 127, ch = c & 7;
        u32 dst; const u16* src;
        if (c < 1024) { dst = st + S2_A + r * RS + ch * 16; src = Ah + (size_t)r * HID + k0 + ch * 8; }
        else          { dst = st + S2_B + r * RS + ch * 16; src = g_W2hi + (wbase + r) * HID + k0 + ch * 8; }
        cpa16(dst, src);
    }
}

__global__ __launch_bounds__(512, 2)
void k_gemm2() {
    if ((int)blockIdx.x >= g_ntiles) return;
    extern __shared__ char smraw[];
    u32 sbase = smem_u32(smraw);
    int tid = threadIdx.x, wid = tid >> 5, lane = tid & 31;
    int warpM = wid >> 2, warpN = wid & 3;
    int e = g_tile_expert[blockIdx.x], row0 = g_tile_row0[blockIdx.x];
    int n0w = blockIdx.y * 128;

    const u16* Ah = g_Hhi + (size_t)row0 * HID;
    size_t wbase = (size_t)e * DIM + n0w;

    u32 aoff = (u32)((lane & 15) * RS + (lane >> 4) * 16);
    u32 b4off = (u32)(((lane & 7) + ((lane >> 4) << 3)) * RS + ((lane >> 3) & 1) * 16);
    u32 aW = (u32)(warpM * 32 * RS);
    u32 bW = (u32)(warpN * 32 * RS);

    float acc[2][4][4];
#pragma unroll
    for (int mt = 0; mt < 2; mt++)
#pragma unroll
        for (int nt = 0; nt < 4; nt++)
#pragma unroll
            for (int j = 0; j < 4; j++) acc[mt][nt][j] = 0.f;

    const int KT = HID / 64;  // 32
    load2(sbase, 0, 0, Ah, wbase, tid); cpa_commit();
    load2(sbase, 1, 1, Ah, wbase, tid); cpa_commit();

    int stage = 0, nstage = 2;
    for (int kt = 0; kt < KT; kt++) {
        cpa_wait1();
        __syncthreads();
        if (kt + 2 < KT) load2(sbase, nstage, kt + 2, Ah, wbase, tid);
        cpa_commit();
        u32 st = sbase + stage * SS2;
#pragma unroll
        for (int kh = 0; kh < 4; kh++) {
            u32 AH[2][4];
#pragma unroll
            for (int mt = 0; mt < 2; mt++)
                ldsm4(AH[mt], st + S2_A + aW + mt * 16 * RS + kh * 32 + aoff);
#pragma unroll
            for (int ntp = 0; ntp < 2; ntp++) {
                u32 bh[4];
                ldsm4(bh, st + S2_B + bW + ntp * 16 * RS + kh * 32 + b4off);
#pragma unroll
                for (int sub = 0; sub < 2; sub++)
#pragma unroll
                    for (int mt = 0; mt < 2; mt++)
                        mma16816(acc[mt][ntp * 2 + sub], AH[mt], bh + sub * 2);
            }
        }
        stage = (stage == 2) ? 0 : stage + 1;
        nstage = (nstage == 2) ? 0 : nstage + 1;
    }

    int g4 = lane >> 2, t4 = lane & 3;
#pragma unroll
    for (int mt = 0; mt < 2; mt++) {
        int rA = row0 + warpM * 32 + mt * 16 + g4;
        float c0 = g_row_coef[rA], c1 = g_row_coef[rA + 8];
#pragma unroll
        for (int nt = 0; nt < 4; nt++) {
            int col = n0w + warpN * 32 + nt * 8 + t4 * 2;
            const float* d = acc[mt][nt];
            *(float2*)(g_Orows + (size_t)rA * DIM + col) = make_float2(c0 * d[0], c0 * d[1]);
            *(float2*)(g_Orows + (size_t)(rA + 8) * DIM + col) = make_float2(c1 * d[2], c1 * d[3]);
        }
    }
}

__global__ void k_combine(float* __restrict__ out) {
    int t = blockIdx.x;
    int i = threadIdx.x * 4;
    int r0 = g_token_row[2 * t], r1 = g_token_row[2 * t + 1];
    float4 a = *(const float4*)(g_Orows + (size_t)r0 * DIM + i);
    float4 b = *(const float4*)(g_Orows + (size_t)r1 * DIM + i);
    *(float4*)(out + (size_t)t * DIM + i) =
        make_float4(a.x + b.x, a.y + b.y, a.z + b.z, a.w + b.w);
}

extern "C" void kernel_launch(void* const* d_in, const int* in_sizes, int n_in,
                              void* d_out, int out_size) {
    const float* x  = (const float*)d_in[0];
    const float* W1 = (const float*)d_in[1];
    const float* W2 = (const float*)d_in[2];
    const float* W3 = (const float*)d_in[3];
    const float* gw = (const float*)d_in[4];
    const float* gb = (const float*)d_in[5];
    float* out = (float*)d_out;

    cudaFuncSetAttribute(k_gemm13, cudaFuncAttributeMaxDynamicSharedMemorySize, SMEM13);
    cudaFuncSetAttribute(k_gemm2,  cudaFuncAttributeMaxDynamicSharedMemorySize, SMEM2);

    // fork-join: W1/W3 conversion joins before gemm13; W2 conversion overlaps
    // gemm13 and joins before gemm2.
    cudaStream_t s1;
    cudaEvent_t evFork, evJoin13, evJoin2;
    cudaStreamCreateWithFlags(&s1, cudaStreamNonBlocking);
    cudaEventCreateWithFlags(&evFork, cudaEventDisableTiming);
    cudaEventCreateWithFlags(&evJoin13, cudaEventDisableTiming);
    cudaEventCreateWithFlags(&evJoin2, cudaEventDisableTiming);

    cudaEventRecord(evFork, 0);
    cudaStreamWaitEvent(s1, evFork, 0);
    k_prepw13<<<32768, 256, 0, s1>>>(W1, W3);
    cudaEventRecord(evJoin13, s1);
    k_prepw2<<<16384, 256, 0, s1>>>(W2);
    cudaEventRecord(evJoin2, s1);

    k_init<<<1, 256>>>();
    k_gate<<<1024, 256>>>(x, gw, gb);
    k_route<<<32, 256>>>();
    k_gather<<<MAXROWS, 256>>>(x);

    cudaStreamWaitEvent(0, evJoin13, 0);
    k_gemm13<<<dim3(MAXMT, HID / 128), 512, SMEM13>>>();
    cudaStreamWaitEvent(0, evJoin2, 0);
    k_gemm2<<<dim3(MAXMT, DIM / 128), 512, SMEM2>>>();
    k_combine<<<NTOK, 256>>>(out);
}